// round 13
// baseline (speedup 1.0000x reference)
#include <cuda_runtime.h>
#include <cuda_fp16.h>
#include <math.h>
#include <stdint.h>

// ---------------------------------------------------------------------------
// GWNet2: B=64, N=1024, L=13, RC=DC=32, SC=256, EC=512, OUT=12, LAYERS=8
// h layout: [B][L][C][N] fp32.
// dconv: fp32x2 FMA over nl-pairs, pre-duplicated weights in smem.
// GEMMs: mma.sync m16n8k16, 3-stage cp.async pipeline, ldmatrix A frags,
// B operands k-packed half2, gc tail fused in epilogue.
// ---------------------------------------------------------------------------

__device__ float  g_hA  [64 * 13 * 32 * 1024];
__device__ float  g_hB  [64 * 12 * 32 * 1024];
__device__ __half g_mmA [64 * 12 * 32 * 2048];       // [mm1 | mm2], A operand
__device__ __half g_mm0 [64 * 12 * 32 * 1024];       // Wm@m + gcb
__device__ float  g_adpf[1024 * 1024];               // ADP fp32 (for ADP^2)
__device__ __half g_Bm  [2048 * 1024];               // k-packed [ADP ; ADP^2]
__device__ __half g_msk [256 * 65536];               // k-packed concat m_last
__device__ __half g_skip[256 * 65536];               // k-packed relu(skip)
__device__ __half g_e1  [512 * 65536];
__device__ __half g_w1r [512 * 256];
__device__ __half g_wsk [256 * 256];
__device__ float  g_bsk [256];

// ---------------------------------------------------------------------------
__device__ __forceinline__ void cp16(void* smem, const void* g) {
    unsigned s = (unsigned)__cvta_generic_to_shared(smem);
    asm volatile("cp.async.cg.shared.global [%0], [%1], 16;\n" :: "r"(s), "l"(g));
}
__device__ __forceinline__ unsigned long long packf2(float lo, float hi) {
    unsigned long long r;
    asm("mov.b64 %0, {%1, %2};" : "=l"(r) : "f"(lo), "f"(hi));
    return r;
}
__device__ __forceinline__ void unpackf2(unsigned long long v, float& lo, float& hi) {
    asm("mov.b64 {%0, %1}, %2;" : "=f"(lo), "=f"(hi) : "l"(v));
}
#define FMA2(acc, a, b) \
    asm("fma.rn.f32x2 %0, %1, %2, %0;" : "+l"(acc) : "l"(a), "l"(b))

// ---------------------------------------------------------------------------
// adp = softmax(relu(nv1 @ nv2)) -> fp32 adpf + k-packed half rows 0..511
// ---------------------------------------------------------------------------
__global__ __launch_bounds__(256) void k_adp(const float* __restrict__ nv1,
                                             const float* __restrict__ nv2,
                                             float* __restrict__ adpf,
                                             __half* __restrict__ Bpk) {
    __shared__ float red[256];
    int v = blockIdx.x, tid = threadIdx.x;
    float n1[10];
#pragma unroll
    for (int k = 0; k < 10; k++) n1[k] = nv1[v * 10 + k];
    float a[4];
#pragma unroll
    for (int j = 0; j < 4; j++) {
        int w = tid + j * 256;
        float s = 0.f;
#pragma unroll
        for (int k = 0; k < 10; k++) s += n1[k] * nv2[k * 1024 + w];
        a[j] = fmaxf(s, 0.f);
    }
    float mx = fmaxf(fmaxf(a[0], a[1]), fmaxf(a[2], a[3]));
    red[tid] = mx; __syncthreads();
    for (int s = 128; s > 0; s >>= 1) {
        if (tid < s) red[tid] = fmaxf(red[tid], red[tid + s]);
        __syncthreads();
    }
    mx = red[0]; __syncthreads();
    float e[4]; float sum = 0.f;
#pragma unroll
    for (int j = 0; j < 4; j++) { e[j] = expf(a[j] - mx); sum += e[j]; }
    red[tid] = sum; __syncthreads();
    for (int s = 128; s > 0; s >>= 1) {
        if (tid < s) red[tid] += red[tid + s];
        __syncthreads();
    }
    float inv = 1.f / red[0];
#pragma unroll
    for (int j = 0; j < 4; j++) {
        int w = tid + j * 256;
        float val = e[j] * inv;
        adpf[(long)v * 1024 + w] = val;
        Bpk[((long)(v >> 1) * 1024 + w) * 2 + (v & 1)] = __float2half(val);
    }
}

// ---------------------------------------------------------------------------
__global__ __launch_bounds__(256) void k_start(const float* __restrict__ x,
                                               const float* __restrict__ sw,
                                               const float* __restrict__ sb,
                                               float* __restrict__ h) {
    int bl = blockIdx.x;
    int b = bl / 13, l = bl - b * 13;
    int n = blockIdx.y * 256 + threadIdx.x;
    float x0 = x[(((long)b * 2 + 0) * 1024 + n) * 13 + l];
    float x1 = x[(((long)b * 2 + 1) * 1024 + n) * 13 + l];
    float* hb = h + ((long)(b * 13 + l) * 32) * 1024 + n;
#pragma unroll
    for (int c = 0; c < 32; c++)
        hb[(long)c * 1024] = sw[c * 2] * x0 + sw[c * 2 + 1] * x1 + sb[c];
}

// ---------------------------------------------------------------------------
// dilated conv + tanh*sigmoid + gc premix.
// Thread owns (co, 8 nl). Accumulators pair adjacent nl (fma.rn.f32x2 on
// native float2 loads); conv weights pre-duplicated u64 pairs in smem.
// ---------------------------------------------------------------------------
__global__ __launch_bounds__(256) void k_dconv(const float* __restrict__ h,
                                               const float* __restrict__ fw,
                                               const float* __restrict__ fb,
                                               const float* __restrict__ gw,
                                               const float* __restrict__ gb,
                                               const float* __restrict__ gcw,
                                               const float* __restrict__ gcb,
                                               __half* __restrict__ mmA,
                                               __half* __restrict__ mm0,
                                               __half* __restrict__ msk,
                                               int L0, int L1, int d, int layer,
                                               int doPre) {
    __shared__ float s_in[2][32][64];                  // 16 KB; [0] reused as s_m
    __shared__ ulonglong2 s_wf[32][32];                // dup (f tap0, f tap1) 16 KB
    __shared__ ulonglong2 s_wg[32][32];                // dup (g tap0, g tap1) 16 KB
    __shared__ float2 s_wpA[32][32];                   // (p0, p1)              8 KB
    __shared__ float  s_wpB[32][32];                   // p2                    4 KB
    __shared__ unsigned long long s_fbp[32], s_gbp[32], s_gcbp[32];

    int bl = blockIdx.x;
    int b = bl / L1, l = bl - b * L1;
    int n0 = blockIdx.y * 64;
    int tid = threadIdx.x;

    for (int idx = tid; idx < 1024; idx += 256) {
        int co = idx >> 5, ci = idx & 31;
        int o = (co * 32 + ci) * 2;
        s_wf[ci][co] = make_ulonglong2(packf2(fw[o], fw[o]),
                                       packf2(fw[o + 1], fw[o + 1]));
        s_wg[ci][co] = make_ulonglong2(packf2(gw[o], gw[o]),
                                       packf2(gw[o + 1], gw[o + 1]));
        if (doPre) {
            s_wpA[ci][co] = make_float2(gcw[co * 96 + ci], gcw[co * 96 + 32 + ci]);
            s_wpB[ci][co] = gcw[co * 96 + 64 + ci];
        }
    }
    if (tid < 32) {
        s_fbp[tid] = packf2(fb[tid], fb[tid]);
        s_gbp[tid] = packf2(gb[tid], gb[tid]);
        s_gcbp[tid] = doPre ? packf2(gcb[tid], gcb[tid]) : 0ull;
    }
    const float* hb = h + ((long)(b * L0 + l) * 32) * 1024 + n0;
    for (int idx = tid; idx < 4096; idx += 256) {
        int tap = idx >> 11, ci = (idx >> 6) & 31, nl = idx & 63;
        s_in[tap][ci][nl] = hb[((long)(tap * d) * 32 + ci) * 1024 + nl];
    }
    __syncthreads();

    int co = tid >> 3, n8 = (tid & 7) * 8;
    unsigned long long fa[4], ga[4];
#pragma unroll
    for (int j = 0; j < 4; j++) { fa[j] = s_fbp[co]; ga[j] = s_gbp[co]; }
#pragma unroll
    for (int ci = 0; ci < 32; ci++) {
        ulonglong2 wf = s_wf[ci][co];
        ulonglong2 wg = s_wg[ci][co];
        ulonglong2 v0a = *(const ulonglong2*)&s_in[0][ci][n8];
        ulonglong2 v0b = *(const ulonglong2*)&s_in[0][ci][n8 + 4];
        ulonglong2 v1a = *(const ulonglong2*)&s_in[1][ci][n8];
        ulonglong2 v1b = *(const ulonglong2*)&s_in[1][ci][n8 + 4];
        FMA2(fa[0], wf.x, v0a.x); FMA2(fa[0], wf.y, v1a.x);
        FMA2(fa[1], wf.x, v0a.y); FMA2(fa[1], wf.y, v1a.y);
        FMA2(fa[2], wf.x, v0b.x); FMA2(fa[2], wf.y, v1b.x);
        FMA2(fa[3], wf.x, v0b.y); FMA2(fa[3], wf.y, v1b.y);
        FMA2(ga[0], wg.x, v0a.x); FMA2(ga[0], wg.y, v1a.x);
        FMA2(ga[1], wg.x, v0a.y); FMA2(ga[1], wg.y, v1a.y);
        FMA2(ga[2], wg.x, v0b.x); FMA2(ga[2], wg.y, v1b.x);
        FMA2(ga[3], wg.x, v0b.y); FMA2(ga[3], wg.y, v1b.y);
    }

    float mval[8];
#pragma unroll
    for (int j = 0; j < 4; j++) {
        float flo, fhi, glo, ghi;
        unpackf2(fa[j], flo, fhi);
        unpackf2(ga[j], glo, ghi);
        mval[2 * j]     = tanhf(flo) * (1.f / (1.f + expf(-glo)));
        mval[2 * j + 1] = tanhf(fhi) * (1.f / (1.f + expf(-ghi)));
    }
    if (l == L1 - 1) {
        int k = layer * 32 + co;
        __half* mp = msk + ((long)(k >> 1) * 65536 + (long)b * 1024 + n0 + n8) * 2
                         + (k & 1);
#pragma unroll
        for (int j = 0; j < 8; j++) mp[j * 2] = __float2half(mval[j]);
    }
    if (!doPre) return;

    // stage m into s_in[0] (conv reads fully done after this sync)
    __syncthreads();
    float (*s_m)[64] = s_in[0];
    *(float4*)&s_m[co][n8]     = make_float4(mval[0], mval[1], mval[2], mval[3]);
    *(float4*)&s_m[co][n8 + 4] = make_float4(mval[4], mval[5], mval[6], mval[7]);
    __syncthreads();

    unsigned long long p0[4], p1[4], p2[4];
#pragma unroll
    for (int j = 0; j < 4; j++) { p0[j] = s_gcbp[co]; p1[j] = 0ull; p2[j] = 0ull; }
#pragma unroll
    for (int ci = 0; ci < 32; ci++) {
        float2 wA = s_wpA[ci][co];
        float  wB = s_wpB[ci][co];
        unsigned long long w0 = packf2(wA.x, wA.x);
        unsigned long long w1 = packf2(wA.y, wA.y);
        unsigned long long w2 = packf2(wB, wB);
        ulonglong2 va = *(const ulonglong2*)&s_m[ci][n8];
        ulonglong2 vb = *(const ulonglong2*)&s_m[ci][n8 + 4];
        FMA2(p0[0], w0, va.x); FMA2(p0[1], w0, va.y);
        FMA2(p0[2], w0, vb.x); FMA2(p0[3], w0, vb.y);
        FMA2(p1[0], w1, va.x); FMA2(p1[1], w1, va.y);
        FMA2(p1[2], w1, vb.x); FMA2(p1[3], w1, vb.y);
        FMA2(p2[0], w2, va.x); FMA2(p2[1], w2, va.y);
        FMA2(p2[2], w2, vb.x); FMA2(p2[3], w2, vb.y);
    }
    long row = (long)(b * L1 + l) * 32 + co;
    uint4 q0, q1, q2;
    {
        float lo, hi; __half2 t;
        unpackf2(p0[0], lo, hi); t = __floats2half2_rn(lo, hi); q0.x = *(unsigned*)&t;
        unpackf2(p0[1], lo, hi); t = __floats2half2_rn(lo, hi); q0.y = *(unsigned*)&t;
        unpackf2(p0[2], lo, hi); t = __floats2half2_rn(lo, hi); q0.z = *(unsigned*)&t;
        unpackf2(p0[3], lo, hi); t = __floats2half2_rn(lo, hi); q0.w = *(unsigned*)&t;
        unpackf2(p1[0], lo, hi); t = __floats2half2_rn(lo, hi); q1.x = *(unsigned*)&t;
        unpackf2(p1[1], lo, hi); t = __floats2half2_rn(lo, hi); q1.y = *(unsigned*)&t;
        unpackf2(p1[2], lo, hi); t = __floats2half2_rn(lo, hi); q1.z = *(unsigned*)&t;
        unpackf2(p1[3], lo, hi); t = __floats2half2_rn(lo, hi); q1.w = *(unsigned*)&t;
        unpackf2(p2[0], lo, hi); t = __floats2half2_rn(lo, hi); q2.x = *(unsigned*)&t;
        unpackf2(p2[1], lo, hi); t = __floats2half2_rn(lo, hi); q2.y = *(unsigned*)&t;
        unpackf2(p2[2], lo, hi); t = __floats2half2_rn(lo, hi); q2.z = *(unsigned*)&t;
        unpackf2(p2[3], lo, hi); t = __floats2half2_rn(lo, hi); q2.w = *(unsigned*)&t;
    }
    *(uint4*)&mm0[row * 1024 + n0 + n8]        = q0;
    *(uint4*)&mmA[row * 2048 + n0 + n8]        = q1;
    *(uint4*)&mmA[row * 2048 + 1024 + n0 + n8] = q2;
}

// ---------------------------------------------------------------------------
// fp32 SIMT SGEMM: ADP^2 = ADP @ ADP; k-packed half into Bpk rows 512..1023
// ---------------------------------------------------------------------------
__global__ __launch_bounds__(256) void k_sgemm(const float* __restrict__ A,
                                               const float* __restrict__ B,
                                               __half* __restrict__ Bpk) {
    __shared__ float As[16][132];
    __shared__ float Bs[16][128];
    int tid = threadIdx.x;
    int m0 = blockIdx.y * 128, n0 = blockIdx.x * 128;
    int ty = tid >> 4, tx = tid & 15;
    float acc[8][8];
#pragma unroll
    for (int i = 0; i < 8; i++)
#pragma unroll
        for (int j = 0; j < 8; j++) acc[i][j] = 0.f;

    for (int k0 = 0; k0 < 1024; k0 += 16) {
#pragma unroll
        for (int i = 0; i < 2; i++) {
            int f = tid + i * 256;
            int r = f >> 2, kc = (f & 3) * 4;
            float4 v = *(const float4*)(A + (long)(m0 + r) * 1024 + k0 + kc);
            As[kc + 0][r] = v.x; As[kc + 1][r] = v.y;
            As[kc + 2][r] = v.z; As[kc + 3][r] = v.w;
        }
#pragma unroll
        for (int i = 0; i < 2; i++) {
            int f = tid + i * 256;
            int r = f >> 5, nc = (f & 31) * 4;
            float4 v = *(const float4*)(B + (long)(k0 + r) * 1024 + n0 + nc);
            *(float4*)&Bs[r][nc] = v;
        }
        __syncthreads();
#pragma unroll
        for (int k = 0; k < 16; k++) {
            float a[8], b[8];
            float4 a0 = *(const float4*)&As[k][ty * 8];
            float4 a1 = *(const float4*)&As[k][ty * 8 + 4];
            a[0] = a0.x; a[1] = a0.y; a[2] = a0.z; a[3] = a0.w;
            a[4] = a1.x; a[5] = a1.y; a[6] = a1.z; a[7] = a1.w;
            float4 b0 = *(const float4*)&Bs[k][tx * 8];
            float4 b1 = *(const float4*)&Bs[k][tx * 8 + 4];
            b[0] = b0.x; b[1] = b0.y; b[2] = b0.z; b[3] = b0.w;
            b[4] = b1.x; b[5] = b1.y; b[6] = b1.z; b[7] = b1.w;
#pragma unroll
            for (int i = 0; i < 8; i++)
#pragma unroll
                for (int j = 0; j < 8; j++) acc[i][j] += a[i] * b[j];
        }
        __syncthreads();
    }
#pragma unroll
    for (int i = 0; i < 8; i++) {
        int v = m0 + ty * 8 + i;
#pragma unroll
        for (int j = 0; j < 8; j++) {
            int w = n0 + tx * 8 + j;
            Bpk[((long)(512 + (v >> 1)) * 1024 + w) * 2 + (v & 1)] =
                __float2half(acc[i][j]);
        }
    }
}

// ---------------------------------------------------------------------------
// fused layer GEMM + gc tail, 3-stage cp.async pipeline, single sync/stage.
// ---------------------------------------------------------------------------
__global__ __launch_bounds__(256) void k_gemm_gc(const __half* __restrict__ A,
                                                 const half2* __restrict__ Bpk,
                                                 float* __restrict__ hnew,
                                                 const float* __restrict__ hold,
                                                 const __half* __restrict__ mm0,
                                                 const float* __restrict__ bng,
                                                 const float* __restrict__ bnb,
                                                 int L0, int L1, int d) {
    __shared__ __half As[3][128][40];
    __shared__ half2  Bs[3][16][264];
    int tid = threadIdx.x;
    int m0 = blockIdx.y * 128;
    int n0 = blockIdx.x * 256;
    int w = tid >> 5, lane = tid & 31;
    int grp = lane >> 2, tg = lane & 3;
    int wm = (w & 1) * 64, wn = (w >> 1) * 64;
    int arow = lane & 15, akoff = (lane >> 4) * 8;
    unsigned asBase = (unsigned)__cvta_generic_to_shared(&As[0][0][0]);

    float acc[4][8][4];
#pragma unroll
    for (int mt = 0; mt < 4; mt++)
#pragma unroll
        for (int nt = 0; nt < 8; nt++)
#pragma unroll
            for (int c = 0; c < 4; c++) acc[mt][nt][c] = 0.f;

    const int nstage = 2048 / 32;
    // prefetch stages 0,1
#pragma unroll
    for (int ps = 0; ps < 2; ps++) {
        int k0 = ps * 32;
#pragma unroll
        for (int i = 0; i < 2; i++) {
            int ch = tid + i * 256;
            int r = ch >> 2, p = (ch & 3) * 8;
            cp16(&As[ps][r][p], A + (long)(m0 + r) * 2048 + k0 + p);
        }
#pragma unroll
        for (int i = 0; i < 4; i++) {
            int ch = tid + i * 256;
            int r = ch >> 6, c4 = (ch & 63) * 4;
            cp16(&Bs[ps][r][c4], Bpk + (long)(k0 / 2 + r) * 1024 + n0 + c4);
        }
        asm volatile("cp.async.commit_group;\n");
    }

    for (int s = 0; s < nstage; s++) {
        int buf = s % 3;
        if (s + 1 < nstage) asm volatile("cp.async.wait_group 1;\n");
        else                asm volatile("cp.async.wait_group 0;\n");
        __syncthreads();
        if (s + 2 < nstage) {
            int nb = (s + 2) % 3;
            int k0 = (s + 2) * 32;
#pragma unroll
            for (int i = 0; i < 2; i++) {
                int ch = tid + i * 256;
                int r = ch >> 2, p = (ch & 3) * 8;
                cp16(&As[nb][r][p], A + (long)(m0 + r) * 2048 + k0 + p);
            }
#pragma unroll
            for (int i = 0; i < 4; i++) {
                int ch = tid + i * 256;
                int r = ch >> 6, c4 = (ch & 63) * 4;
                cp16(&Bs[nb][r][c4], Bpk + (long)(k0 / 2 + r) * 1024 + n0 + c4);
            }
            asm volatile("cp.async.commit_group;\n");
        }

#pragma unroll
        for (int s2 = 0; s2 < 2; s2++) {
            unsigned a[4][4];
#pragma unroll
            for (int mt = 0; mt < 4; mt++) {
                unsigned addr = asBase +
                    (unsigned)(((buf * 128) + wm + mt * 16 + arow) * 40 +
                               s2 * 16 + akoff) * 2;
                asm volatile(
                    "ldmatrix.sync.aligned.m8n8.x4.shared.b16 {%0,%1,%2,%3}, [%4];\n"
                    : "=r"(a[mt][0]), "=r"(a[mt][1]), "=r"(a[mt][2]), "=r"(a[mt][3])
                    : "r"(addr));
            }
            unsigned b[8][2];
#pragma unroll
            for (int nt = 0; nt < 8; nt++) {
                int cb = wn + nt * 8 + grp;
                b[nt][0] = *(const unsigned*)&Bs[buf][s2 * 8 + tg][cb];
                b[nt][1] = *(const unsigned*)&Bs[buf][s2 * 8 + tg + 4][cb];
            }
#pragma unroll
            for (int mt = 0; mt < 4; mt++)
#pragma unroll
                for (int nt = 0; nt < 8; nt++) {
                    asm volatile(
                        "mma.sync.aligned.m16n8k16.row.col.f32.f16.f16.f32 "
                        "{%0,%1,%2,%3}, {%4,%5,%6,%7}, {%8,%9}, {%0,%1,%2,%3};\n"
                        : "+f"(acc[mt][nt][0]), "+f"(acc[mt][nt][1]),
                          "+f"(acc[mt][nt][2]), "+f"(acc[mt][nt][3])
                        : "r"(a[mt][0]), "r"(a[mt][1]), "r"(a[mt][2]), "r"(a[mt][3]),
                          "r"(b[nt][0]), "r"(b[nt][1]));
                }
        }
    }

    const float rs = rsqrtf(1.f + 1e-5f);
#pragma unroll
    for (int mt = 0; mt < 4; mt++) {
        int row0 = m0 + wm + mt * 16 + grp;
        int row1 = row0 + 8;
        int blx = row0 >> 5;
        int b = blx / L1, l = blx - b * L1;
        long hbase = (long)(b * L0 + l + d) * 32;
        int co0 = row0 & 31, co1 = row1 & 31;
        float sc0 = bng[co0] * rs, sh0 = bnb[co0];
        float sc1 = bng[co1] * rs, sh1 = bnb[co1];
#pragma unroll
        for (int nt = 0; nt < 8; nt++) {
            int col = n0 + wn + nt * 8 + tg * 2;
            half2 q0 = *(const half2*)&mm0[(long)row0 * 1024 + col];
            half2 q1 = *(const half2*)&mm0[(long)row1 * 1024 + col];
            float2 r0 = *(const float2*)&hold[(hbase + co0) * 1024 + col];
            float2 r1 = *(const float2*)&hold[(hbase + co1) * 1024 + col];
            float2 o0, o1;
            o0.x = (acc[mt][nt][0] + __half2float(q0.x) + r0.x) * sc0 + sh0;
            o0.y = (acc[mt][nt][1] + __half2float(q0.y) + r0.y) * sc0 + sh0;
            o1.x = (acc[mt][nt][2] + __half2float(q1.x) + r1.x) * sc1 + sh1;
            o1.y = (acc[mt][nt][3] + __half2float(q1.y) + r1.y) * sc1 + sh1;
            *(float2*)&hnew[(long)row0 * 1024 + col] = o0;
            *(float2*)&hnew[(long)row1 * 1024 + col] = o1;
        }
    }
}

// ---------------------------------------------------------------------------
// generic fp16 GEMM (skip/end1), 3-stage pipeline, ldmatrix A.
// flags bit1: +bias relu. bit2: C k-packed half. bit3: C plain half. else f32.
// ---------------------------------------------------------------------------
__global__ __launch_bounds__(256) void k_gemm_f16(const __half* __restrict__ A,
                                                  const half2* __restrict__ Bpk,
                                                  void* __restrict__ Cv,
                                                  int K, int lda, long ldb2, long ldc,
                                                  const float* __restrict__ bias,
                                                  int flags) {
    __shared__ __half As[3][128][40];
    __shared__ half2  Bs[3][16][264];
    int tid = threadIdx.x;
    int m0 = blockIdx.y * 128;
    long n0 = (long)blockIdx.x * 256;
    int w = tid >> 5, lane = tid & 31;
    int grp = lane >> 2, tg = lane & 3;
    int wm = (w & 1) * 64, wn = (w >> 1) * 64;
    int arow = lane & 15, akoff = (lane >> 4) * 8;
    unsigned asBase = (unsigned)__cvta_generic_to_shared(&As[0][0][0]);

    float acc[4][8][4];
#pragma unroll
    for (int mt = 0; mt < 4; mt++)
#pragma unroll
        for (int nt = 0; nt < 8; nt++)
#pragma unroll
            for (int c = 0; c < 4; c++) acc[mt][nt][c] = 0.f;

    int nstage = K / 32;
#pragma unroll
    for (int ps = 0; ps < 2; ps++) {
        if (ps < nstage) {
            int k0 = ps * 32;
#pragma unroll
            for (int i = 0; i < 2; i++) {
                int ch = tid + i * 256;
                int r = ch >> 2, p = (ch & 3) * 8;
                cp16(&As[ps][r][p], A + (long)(m0 + r) * lda + k0 + p);
            }
#pragma unroll
            for (int i = 0; i < 4; i++) {
                int ch = tid + i * 256;
                int r = ch >> 6, c4 = (ch & 63) * 4;
                cp16(&Bs[ps][r][c4], Bpk + (long)(k0 / 2 + r) * ldb2 + n0 + c4);
            }
            asm volatile("cp.async.commit_group;\n");
        }
    }

    for (int s = 0; s < nstage; s++) {
        int buf = s % 3;
        if (s + 1 < nstage) asm volatile("cp.async.wait_group 1;\n");
        else                asm volatile("cp.async.wait_group 0;\n");
        __syncthreads();
        if (s + 2 < nstage) {
            int nb = (s + 2) % 3;
            int k0 = (s + 2) * 32;
#pragma unroll
            for (int i = 0; i < 2; i++) {
                int ch = tid + i * 256;
                int r = ch >> 2, p = (ch & 3) * 8;
                cp16(&As[nb][r][p], A + (long)(m0 + r) * lda + k0 + p);
            }
#pragma unroll
            for (int i = 0; i < 4; i++) {
                int ch = tid + i * 256;
                int r = ch >> 6, c4 = (ch & 63) * 4;
                cp16(&Bs[nb][r][c4], Bpk + (long)(k0 / 2 + r) * ldb2 + n0 + c4);
            }
            asm volatile("cp.async.commit_group;\n");
        }

#pragma unroll
        for (int s2 = 0; s2 < 2; s2++) {
            unsigned a[4][4];
#pragma unroll
            for (int mt = 0; mt < 4; mt++) {
                unsigned addr = asBase +
                    (unsigned)(((buf * 128) + wm + mt * 16 + arow) * 40 +
                               s2 * 16 + akoff) * 2;
                asm volatile(
                    "ldmatrix.sync.aligned.m8n8.x4.shared.b16 {%0,%1,%2,%3}, [%4];\n"
                    : "=r"(a[mt][0]), "=r"(a[mt][1]), "=r"(a[mt][2]), "=r"(a[mt][3])
                    : "r"(addr));
            }
            unsigned b[8][2];
#pragma unroll
            for (int nt = 0; nt < 8; nt++) {
                int cb = wn + nt * 8 + grp;
                b[nt][0] = *(const unsigned*)&Bs[buf][s2 * 8 + tg][cb];
                b[nt][1] = *(const unsigned*)&Bs[buf][s2 * 8 + tg + 4][cb];
            }
#pragma unroll
            for (int mt = 0; mt < 4; mt++)
#pragma unroll
                for (int nt = 0; nt < 8; nt++) {
                    asm volatile(
                        "mma.sync.aligned.m16n8k16.row.col.f32.f16.f16.f32 "
                        "{%0,%1,%2,%3}, {%4,%5,%6,%7}, {%8,%9}, {%0,%1,%2,%3};\n"
                        : "+f"(acc[mt][nt][0]), "+f"(acc[mt][nt][1]),
                          "+f"(acc[mt][nt][2]), "+f"(acc[mt][nt][3])
                        : "r"(a[mt][0]), "r"(a[mt][1]), "r"(a[mt][2]), "r"(a[mt][3]),
                          "r"(b[nt][0]), "r"(b[nt][1]));
                }
        }
    }

    float* Cf = (float*)Cv;
    __half* Ch = (__half*)Cv;
#pragma unroll
    for (int mt = 0; mt < 4; mt++) {
        int row0 = m0 + wm + mt * 16 + grp;
        int row1 = row0 + 8;
        float b0 = 0.f, b1 = 0.f;
        if (flags & 2) { b0 = bias[row0]; b1 = bias[row1]; }
#pragma unroll
        for (int nt = 0; nt < 8; nt++) {
            long col = n0 + wn + nt * 8 + tg * 2;
            float v00 = acc[mt][nt][0], v01 = acc[mt][nt][1];
            float v10 = acc[mt][nt][2], v11 = acc[mt][nt][3];
            if (flags & 2) {
                v00 = fmaxf(v00 + b0, 0.f); v01 = fmaxf(v01 + b0, 0.f);
                v10 = fmaxf(v10 + b1, 0.f); v11 = fmaxf(v11 + b1, 0.f);
            }
            if (flags & 4) {
                long p0 = ((long)(row0 >> 1) * ldc + col) * 2 + (row0 & 1);
                long p1 = ((long)(row1 >> 1) * ldc + col) * 2 + (row1 & 1);
                Ch[p0] = __float2half(v00); Ch[p0 + 2] = __float2half(v01);
                Ch[p1] = __float2half(v10); Ch[p1 + 2] = __float2half(v11);
            } else if (flags & 8) {
                *(half2*)(Ch + (long)row0 * ldc + col) = __floats2half2_rn(v00, v01);
                *(half2*)(Ch + (long)row1 * ldc + col) = __floats2half2_rn(v10, v11);
            } else {
                *(float2*)(Cf + (long)row0 * ldc + col) = make_float2(v00, v01);
                *(float2*)(Cf + (long)row1 * ldc + col) = make_float2(v10, v11);
            }
        }
    }
}

// ---------------------------------------------------------------------------
__global__ __launch_bounds__(256) void k_prep(const float* __restrict__ skw,
                                              const float* __restrict__ skb,
                                              __half* __restrict__ wcat,
                                              float* __restrict__ bsum) {
    int co = blockIdx.x, k = threadIdx.x;
    int i = k >> 5, ci = k & 31;
    wcat[co * 256 + k] = __float2half(skw[((long)i * 256 + co) * 32 + ci]);
    if (k == 0) {
        float s = 0.f;
#pragma unroll
        for (int j = 0; j < 8; j++) s += skb[j * 256 + co];
        bsum[co] = s;
    }
}
__global__ __launch_bounds__(256) void k_roundh(const float* __restrict__ w,
                                                __half* __restrict__ o) {
    int i = blockIdx.x * 256 + threadIdx.x;
    o[i] = __float2half(w[i]);
}

// ---------------------------------------------------------------------------
__global__ __launch_bounds__(256) void k_end2(const __half* __restrict__ e1,
                                              const float* __restrict__ w2,
                                              const float* __restrict__ b2,
                                              float* __restrict__ out) {
    __shared__ float s_w[12 * 512];
    int tid = threadIdx.x;
    for (int idx = tid; idx < 6144; idx += 256) s_w[idx] = w2[idx];
    __syncthreads();
    int col = blockIdx.x * 256 + tid;
    int b = col >> 10, n = col & 1023;
    float acc[12];
#pragma unroll
    for (int o = 0; o < 12; o++) acc[o] = b2[o];
    for (int c = 0; c < 512; c++) {
        float v = __half2float(e1[(long)c * 65536 + col]);
#pragma unroll
        for (int o = 0; o < 12; o++) acc[o] += s_w[o * 512 + c] * v;
    }
#pragma unroll
    for (int o = 0; o < 12; o++) out[((long)b * 12 + o) * 1024 + n] = acc[o];
}

// ---------------------------------------------------------------------------
extern "C" void kernel_launch(void* const* d_in, const int* in_sizes, int n_in,
                              void* d_out, int out_size) {
    const float* x        = (const float*)d_in[0];
    const float* start_w  = (const float*)d_in[1];
    const float* start_b  = (const float*)d_in[2];
    const float* nodevec1 = (const float*)d_in[3];
    const float* nodevec2 = (const float*)d_in[4];
    const float* filter_w = (const float*)d_in[5];
    const float* filter_b = (const float*)d_in[6];
    const float* gate_w   = (const float*)d_in[7];
    const float* gate_b   = (const float*)d_in[8];
    const float* skip_w   = (const float*)d_in[9];
    const float* skip_b   = (const float*)d_in[10];
    const float* gc_w     = (const float*)d_in[11];
    const float* gc_b     = (const float*)d_in[12];
    const float* bn_g     = (const float*)d_in[13];
    const float* bn_b     = (const float*)d_in[14];
    const float* end1_w   = (const float*)d_in[15];
    const float* end1_b   = (const float*)d_in[16];
    const float* end2_w   = (const float*)d_in[17];
    const float* end2_b   = (const float*)d_in[18];

    float *hA, *hB, *adpf, *bsk;
    __half *mmA, *mm0, *Bm, *msk, *skip, *e1, *w1r, *wsk;
    cudaGetSymbolAddress((void**)&hA, g_hA);
    cudaGetSymbolAddress((void**)&hB, g_hB);
    cudaGetSymbolAddress((void**)&mmA, g_mmA);
    cudaGetSymbolAddress((void**)&mm0, g_mm0);
    cudaGetSymbolAddress((void**)&adpf, g_adpf);
    cudaGetSymbolAddress((void**)&Bm, g_Bm);
    cudaGetSymbolAddress((void**)&msk, g_msk);
    cudaGetSymbolAddress((void**)&skip, g_skip);
    cudaGetSymbolAddress((void**)&e1, g_e1);
    cudaGetSymbolAddress((void**)&w1r, g_w1r);
    cudaGetSymbolAddress((void**)&wsk, g_wsk);
    cudaGetSymbolAddress((void**)&bsk, g_bsk);

    k_adp<<<1024, 256>>>(nodevec1, nodevec2, adpf, Bm);
    k_sgemm<<<dim3(8, 8), 256>>>(adpf, adpf, Bm);
    k_start<<<dim3(64 * 13, 4), 256>>>(x, start_w, start_b, hA);
    k_roundh<<<512, 256>>>(end1_w, w1r);
    k_prep<<<256, 256>>>(skip_w, skip_b, wsk, bsk);

    const int lens[9] = {13, 12, 10, 9, 7, 6, 4, 3, 1};
    const int dil[8]  = {1, 2, 1, 2, 1, 2, 1, 2};
    float* hcur = hA;
    float* hnext = hB;

    for (int i = 0; i < 8; i++) {
        int L0 = lens[i], L1 = lens[i + 1], d = dil[i];
        int doPre = (i < 7) ? 1 : 0;
        k_dconv<<<dim3(64 * L1, 16), 256>>>(hcur,
                                            filter_w + i * 2048, filter_b + i * 32,
                                            gate_w + i * 2048, gate_b + i * 32,
                                            gc_w + i * 32 * 96, gc_b + i * 32,
                                            mmA, mm0, msk, L0, L1, d, i, doPre);
        if (i < 7) {
            int M = 2048 * L1;
            k_gemm_gc<<<dim3(4, M / 128), 256>>>(
                mmA, (const half2*)Bm, hnext, hcur, mm0,
                bn_g + i * 32, bn_b + i * 32, L0, L1, d);
            float* t = hcur; hcur = hnext; hnext = t;
        }
    }

    k_gemm_f16<<<dim3(65536 / 256, 2), 256>>>(
        wsk, (const half2*)msk, skip, 256, 256, 65536, 65536, bsk, 2 | 4);
    k_gemm_f16<<<dim3(65536 / 256, 4), 256>>>(
        w1r, (const half2*)skip, e1, 256, 256, 65536, 65536, end1_b, 2 | 8);
    k_end2<<<256, 256>>>(e1, end2_w, end2_b, (float*)d_out);
}

// round 14
// speedup vs baseline: 1.3292x; 1.3292x over previous
#include <cuda_runtime.h>
#include <cuda_fp16.h>
#include <math.h>
#include <stdint.h>

// ---------------------------------------------------------------------------
// GWNet2: B=64, N=1024, L=13, RC=DC=32, SC=256, EC=512, OUT=12, LAYERS=8
// h layout: [B][L][C][N] fp32.  (R12 base; end2 now a padded tensor-core GEMM)
// dconv: fp32x2 FMA (co-pair accumulators), gc premix fused.
// GEMMs: mma.sync m16n8k16 f16/f32acc, 2-stage cp.async, ldmatrix A frags,
// B operands k-packed half2. gc tail fused in x12-GEMM epilogue.
// ---------------------------------------------------------------------------

__device__ float  g_hA  [64 * 13 * 32 * 1024];
__device__ float  g_hB  [64 * 12 * 32 * 1024];
__device__ __half g_mmA [64 * 12 * 32 * 2048];       // [mm1 | mm2], A operand
__device__ __half g_mm0 [64 * 12 * 32 * 1024];       // Wm@m + gcb
__device__ float  g_adpf[1024 * 1024];               // ADP fp32 (for ADP^2)
__device__ __half g_Bm  [2048 * 1024];               // k-packed [ADP ; ADP^2]
__device__ __half g_msk [256 * 65536];               // k-packed concat m_last
__device__ __half g_skip[256 * 65536];               // k-packed relu(skip)
__device__ __half g_e1  [512 * 65536];               // k-packed relu(e1)
__device__ __half g_w1r [512 * 256];
__device__ __half g_wsk [256 * 256];
__device__ float  g_bsk [256];
__device__ __half g_w2p [128 * 512];                 // padded end2 weights
__device__ float  g_b2p [128];

// ---------------------------------------------------------------------------
__device__ __forceinline__ void cp16(void* smem, const void* g) {
    unsigned s = (unsigned)__cvta_generic_to_shared(smem);
    asm volatile("cp.async.cg.shared.global [%0], [%1], 16;\n" :: "r"(s), "l"(g));
}
__device__ __forceinline__ unsigned long long packf2(float lo, float hi) {
    unsigned long long r;
    asm("mov.b64 %0, {%1, %2};" : "=l"(r) : "f"(lo), "f"(hi));
    return r;
}
__device__ __forceinline__ void unpackf2(unsigned long long v, float& lo, float& hi) {
    asm("mov.b64 {%0, %1}, %2;" : "=f"(lo), "=f"(hi) : "l"(v));
}
#define FMA2(acc, a, b) \
    asm("fma.rn.f32x2 %0, %1, %2, %0;" : "+l"(acc) : "l"(a), "l"(b))

// ---------------------------------------------------------------------------
// adp = softmax(relu(nv1 @ nv2)) -> fp32 adpf + k-packed half rows 0..511
// ---------------------------------------------------------------------------
__global__ __launch_bounds__(256) void k_adp(const float* __restrict__ nv1,
                                             const float* __restrict__ nv2,
                                             float* __restrict__ adpf,
                                             __half* __restrict__ Bpk) {
    __shared__ float red[256];
    int v = blockIdx.x, tid = threadIdx.x;
    float n1[10];
#pragma unroll
    for (int k = 0; k < 10; k++) n1[k] = nv1[v * 10 + k];
    float a[4];
#pragma unroll
    for (int j = 0; j < 4; j++) {
        int w = tid + j * 256;
        float s = 0.f;
#pragma unroll
        for (int k = 0; k < 10; k++) s += n1[k] * nv2[k * 1024 + w];
        a[j] = fmaxf(s, 0.f);
    }
    float mx = fmaxf(fmaxf(a[0], a[1]), fmaxf(a[2], a[3]));
    red[tid] = mx; __syncthreads();
    for (int s = 128; s > 0; s >>= 1) {
        if (tid < s) red[tid] = fmaxf(red[tid], red[tid + s]);
        __syncthreads();
    }
    mx = red[0]; __syncthreads();
    float e[4]; float sum = 0.f;
#pragma unroll
    for (int j = 0; j < 4; j++) { e[j] = expf(a[j] - mx); sum += e[j]; }
    red[tid] = sum; __syncthreads();
    for (int s = 128; s > 0; s >>= 1) {
        if (tid < s) red[tid] += red[tid + s];
        __syncthreads();
    }
    float inv = 1.f / red[0];
#pragma unroll
    for (int j = 0; j < 4; j++) {
        int w = tid + j * 256;
        float val = e[j] * inv;
        adpf[(long)v * 1024 + w] = val;
        Bpk[((long)(v >> 1) * 1024 + w) * 2 + (v & 1)] = __float2half(val);
    }
}

// ---------------------------------------------------------------------------
__global__ __launch_bounds__(256) void k_start(const float* __restrict__ x,
                                               const float* __restrict__ sw,
                                               const float* __restrict__ sb,
                                               float* __restrict__ h) {
    int bl = blockIdx.x;
    int b = bl / 13, l = bl - b * 13;
    int n = blockIdx.y * 256 + threadIdx.x;
    float x0 = x[(((long)b * 2 + 0) * 1024 + n) * 13 + l];
    float x1 = x[(((long)b * 2 + 1) * 1024 + n) * 13 + l];
    float* hb = h + ((long)(b * 13 + l) * 32) * 1024 + n;
#pragma unroll
    for (int c = 0; c < 32; c++)
        hb[(long)c * 1024] = sw[c * 2] * x0 + sw[c * 2 + 1] * x1 + sb[c];
}

// ---------------------------------------------------------------------------
// dilated conv + tanh*sigmoid + gc channel premix, packed fp32x2 FMA (R12).
// ---------------------------------------------------------------------------
__global__ __launch_bounds__(256) void k_dconv(const float* __restrict__ h,
                                               const float* __restrict__ fw,
                                               const float* __restrict__ fb,
                                               const float* __restrict__ gw,
                                               const float* __restrict__ gb,
                                               const float* __restrict__ gcw,
                                               const float* __restrict__ gcb,
                                               __half* __restrict__ mmA,
                                               __half* __restrict__ mm0,
                                               __half* __restrict__ msk,
                                               int L0, int L1, int d, int layer,
                                               int doPre) {
    __shared__ float  s_in[2][32][64];
    __shared__ float4 s_wf[32][16];
    __shared__ float4 s_wg[32][16];
    __shared__ float4 s_wpA[32][16];
    __shared__ float2 s_wpB[32][16];
    __shared__ unsigned long long s_fbp[16], s_gbp[16], s_gcbp[16];

    int bl = blockIdx.x;
    int b = bl / L1, l = bl - b * L1;
    int n0 = blockIdx.y * 64;
    int tid = threadIdx.x;

    for (int idx = tid; idx < 512; idx += 256) {
        int ci = idx >> 4, p = idx & 15;
        int co0 = p * 2, co1 = p * 2 + 1;
        int o0 = (co0 * 32 + ci) * 2, o1 = (co1 * 32 + ci) * 2;
        s_wf[ci][p] = make_float4(fw[o0], fw[o1], fw[o0 + 1], fw[o1 + 1]);
        s_wg[ci][p] = make_float4(gw[o0], gw[o1], gw[o0 + 1], gw[o1 + 1]);
        if (doPre) {
            s_wpA[ci][p] = make_float4(gcw[co0 * 96 + ci], gcw[co1 * 96 + ci],
                                       gcw[co0 * 96 + 32 + ci], gcw[co1 * 96 + 32 + ci]);
            s_wpB[ci][p] = make_float2(gcw[co0 * 96 + 64 + ci], gcw[co1 * 96 + 64 + ci]);
        }
    }
    if (tid < 16) {
        s_fbp[tid] = packf2(fb[2 * tid], fb[2 * tid + 1]);
        s_gbp[tid] = packf2(gb[2 * tid], gb[2 * tid + 1]);
        s_gcbp[tid] = doPre ? packf2(gcb[2 * tid], gcb[2 * tid + 1]) : 0ull;
    }
    const float* hb = h + ((long)(b * L0 + l) * 32) * 1024 + n0;
    for (int idx = tid; idx < 4096; idx += 256) {
        int tap = idx >> 11, ci = (idx >> 6) & 31, nl = idx & 63;
        s_in[tap][ci][nl] = hb[((long)(tap * d) * 32 + ci) * 1024 + nl];
    }
    __syncthreads();

    int nl = tid & 63, cg = tid >> 6;
    unsigned long long fa2[4], ga2[4];
#pragma unroll
    for (int p = 0; p < 4; p++) { fa2[p] = s_fbp[cg * 4 + p]; ga2[p] = s_gbp[cg * 4 + p]; }
#pragma unroll
    for (int ci = 0; ci < 32; ci++) {
        float v0 = s_in[0][ci][nl], v1 = s_in[1][ci][nl];
        unsigned long long vv0 = packf2(v0, v0), vv1 = packf2(v1, v1);
#pragma unroll
        for (int p = 0; p < 4; p++) {
            ulonglong2 wf = *(const ulonglong2*)&s_wf[ci][cg * 4 + p];
            FMA2(fa2[p], wf.x, vv0);
            FMA2(fa2[p], wf.y, vv1);
            ulonglong2 wg = *(const ulonglong2*)&s_wg[ci][cg * 4 + p];
            FMA2(ga2[p], wg.x, vv0);
            FMA2(ga2[p], wg.y, vv1);
        }
    }

    bool last = (l == L1 - 1);
    long col = (long)b * 1024 + n0 + nl;
    float mval[8];
#pragma unroll
    for (int p = 0; p < 4; p++) {
        float flo, fhi, glo, ghi;
        unpackf2(fa2[p], flo, fhi);
        unpackf2(ga2[p], glo, ghi);
        mval[2 * p]     = tanhf(flo) * (1.f / (1.f + expf(-glo)));
        mval[2 * p + 1] = tanhf(fhi) * (1.f / (1.f + expf(-ghi)));
    }
#pragma unroll
    for (int u = 0; u < 8; u++) {
        if (last) {
            int k = layer * 32 + cg * 8 + u;
            msk[((long)(k >> 1) * 65536 + col) * 2 + (k & 1)] = __float2half(mval[u]);
        }
    }
    if (!doPre) return;

    __syncthreads();
    float (*s_m)[64] = s_in[0];
#pragma unroll
    for (int u = 0; u < 8; u++) s_m[cg * 8 + u][nl] = mval[u];
    __syncthreads();

    unsigned long long p02[4], p12[4], p22[4];
#pragma unroll
    for (int p = 0; p < 4; p++) { p02[p] = s_gcbp[cg * 4 + p]; p12[p] = 0ull; p22[p] = 0ull; }
#pragma unroll
    for (int ci = 0; ci < 32; ci++) {
        float v = s_m[ci][nl];
        unsigned long long vv = packf2(v, v);
#pragma unroll
        for (int p = 0; p < 4; p++) {
            ulonglong2 wa = *(const ulonglong2*)&s_wpA[ci][cg * 4 + p];
            FMA2(p02[p], wa.x, vv);
            FMA2(p12[p], wa.y, vv);
            unsigned long long wb = *(const unsigned long long*)&s_wpB[ci][cg * 4 + p];
            FMA2(p22[p], wb, vv);
        }
    }
    long rowbase = (long)(b * L1 + l) * 32;
#pragma unroll
    for (int p = 0; p < 4; p++) {
        float a0, a1, b0, b1, c0, c1;
        unpackf2(p02[p], a0, a1);
        unpackf2(p12[p], b0, b1);
        unpackf2(p22[p], c0, c1);
        long r0 = rowbase + cg * 8 + 2 * p;
        long r1 = r0 + 1;
        mm0[r0 * 1024 + n0 + nl] = __float2half(a0);
        mm0[r1 * 1024 + n0 + nl] = __float2half(a1);
        mmA[r0 * 2048 + n0 + nl] = __float2half(b0);
        mmA[r1 * 2048 + n0 + nl] = __float2half(b1);
        mmA[r0 * 2048 + 1024 + n0 + nl] = __float2half(c0);
        mmA[r1 * 2048 + 1024 + n0 + nl] = __float2half(c1);
    }
}

// ---------------------------------------------------------------------------
// fp32 SIMT SGEMM: ADP^2 = ADP @ ADP; k-packed half into Bpk rows 512..1023
// ---------------------------------------------------------------------------
__global__ __launch_bounds__(256) void k_sgemm(const float* __restrict__ A,
                                               const float* __restrict__ B,
                                               __half* __restrict__ Bpk) {
    __shared__ float As[16][132];
    __shared__ float Bs[16][128];
    int tid = threadIdx.x;
    int m0 = blockIdx.y * 128, n0 = blockIdx.x * 128;
    int ty = tid >> 4, tx = tid & 15;
    float acc[8][8];
#pragma unroll
    for (int i = 0; i < 8; i++)
#pragma unroll
        for (int j = 0; j < 8; j++) acc[i][j] = 0.f;

    for (int k0 = 0; k0 < 1024; k0 += 16) {
#pragma unroll
        for (int i = 0; i < 2; i++) {
            int f = tid + i * 256;
            int r = f >> 2, kc = (f & 3) * 4;
            float4 v = *(const float4*)(A + (long)(m0 + r) * 1024 + k0 + kc);
            As[kc + 0][r] = v.x; As[kc + 1][r] = v.y;
            As[kc + 2][r] = v.z; As[kc + 3][r] = v.w;
        }
#pragma unroll
        for (int i = 0; i < 2; i++) {
            int f = tid + i * 256;
            int r = f >> 5, nc = (f & 31) * 4;
            float4 v = *(const float4*)(B + (long)(k0 + r) * 1024 + n0 + nc);
            *(float4*)&Bs[r][nc] = v;
        }
        __syncthreads();
#pragma unroll
        for (int k = 0; k < 16; k++) {
            float a[8], b[8];
            float4 a0 = *(const float4*)&As[k][ty * 8];
            float4 a1 = *(const float4*)&As[k][ty * 8 + 4];
            a[0] = a0.x; a[1] = a0.y; a[2] = a0.z; a[3] = a0.w;
            a[4] = a1.x; a[5] = a1.y; a[6] = a1.z; a[7] = a1.w;
            float4 b0 = *(const float4*)&Bs[k][tx * 8];
            float4 b1 = *(const float4*)&Bs[k][tx * 8 + 4];
            b[0] = b0.x; b[1] = b0.y; b[2] = b0.z; b[3] = b0.w;
            b[4] = b1.x; b[5] = b1.y; b[6] = b1.z; b[7] = b1.w;
#pragma unroll
            for (int i = 0; i < 8; i++)
#pragma unroll
                for (int j = 0; j < 8; j++) acc[i][j] += a[i] * b[j];
        }
        __syncthreads();
    }
#pragma unroll
    for (int i = 0; i < 8; i++) {
        int v = m0 + ty * 8 + i;
#pragma unroll
        for (int j = 0; j < 8; j++) {
            int w = n0 + tx * 8 + j;
            Bpk[((long)(512 + (v >> 1)) * 1024 + w) * 2 + (v & 1)] =
                __float2half(acc[i][j]);
        }
    }
}

// ---------------------------------------------------------------------------
// fused layer GEMM + gc tail (R12: 2-stage cp.async, ldmatrix A).
// ---------------------------------------------------------------------------
__global__ __launch_bounds__(256) void k_gemm_gc(const __half* __restrict__ A,
                                                 const half2* __restrict__ Bpk,
                                                 float* __restrict__ hnew,
                                                 const float* __restrict__ hold,
                                                 const __half* __restrict__ mm0,
                                                 const float* __restrict__ bng,
                                                 const float* __restrict__ bnb,
                                                 int L0, int L1, int d) {
    __shared__ __half As[2][128][40];
    __shared__ half2  Bs[2][16][264];
    int tid = threadIdx.x;
    int m0 = blockIdx.y * 128;
    int n0 = blockIdx.x * 256;
    int w = tid >> 5, lane = tid & 31;
    int grp = lane >> 2, tg = lane & 3;
    int wm = (w & 1) * 64, wn = (w >> 1) * 64;
    int arow = lane & 15, akoff = (lane >> 4) * 8;
    unsigned asBase = (unsigned)__cvta_generic_to_shared(&As[0][0][0]);

    float acc[4][8][4];
#pragma unroll
    for (int mt = 0; mt < 4; mt++)
#pragma unroll
        for (int nt = 0; nt < 8; nt++)
#pragma unroll
            for (int c = 0; c < 4; c++) acc[mt][nt][c] = 0.f;

    const int nstage = 2048 / 32;
    {
#pragma unroll
        for (int i = 0; i < 2; i++) {
            int ch = tid + i * 256;
            int r = ch >> 2, p = (ch & 3) * 8;
            cp16(&As[0][r][p], A + (long)(m0 + r) * 2048 + p);
        }
#pragma unroll
        for (int i = 0; i < 4; i++) {
            int ch = tid + i * 256;
            int r = ch >> 6, c4 = (ch & 63) * 4;
            cp16(&Bs[0][r][c4], Bpk + (long)r * 1024 + n0 + c4);
        }
        asm volatile("cp.async.commit_group;\n");
    }

    for (int s = 0; s < nstage; s++) {
        int buf = s & 1;
        if (s + 1 < nstage) {
            int nb = buf ^ 1;
            int k0 = (s + 1) * 32;
#pragma unroll
            for (int i = 0; i < 2; i++) {
                int ch = tid + i * 256;
                int r = ch >> 2, p = (ch & 3) * 8;
                cp16(&As[nb][r][p], A + (long)(m0 + r) * 2048 + k0 + p);
            }
#pragma unroll
            for (int i = 0; i < 4; i++) {
                int ch = tid + i * 256;
                int r = ch >> 6, c4 = (ch & 63) * 4;
                cp16(&Bs[nb][r][c4], Bpk + (long)(k0 / 2 + r) * 1024 + n0 + c4);
            }
            asm volatile("cp.async.commit_group;\n");
            asm volatile("cp.async.wait_group 1;\n");
        } else {
            asm volatile("cp.async.wait_group 0;\n");
        }
        __syncthreads();

#pragma unroll
        for (int s2 = 0; s2 < 2; s2++) {
            unsigned a[4][4];
#pragma unroll
            for (int mt = 0; mt < 4; mt++) {
                unsigned addr = asBase +
                    (unsigned)(((buf << 7) + wm + mt * 16 + arow) * 40 +
                               s2 * 16 + akoff) * 2;
                asm volatile(
                    "ldmatrix.sync.aligned.m8n8.x4.shared.b16 {%0,%1,%2,%3}, [%4];\n"
                    : "=r"(a[mt][0]), "=r"(a[mt][1]), "=r"(a[mt][2]), "=r"(a[mt][3])
                    : "r"(addr));
            }
            unsigned b[8][2];
#pragma unroll
            for (int nt = 0; nt < 8; nt++) {
                int cb = wn + nt * 8 + grp;
                b[nt][0] = *(const unsigned*)&Bs[buf][s2 * 8 + tg][cb];
                b[nt][1] = *(const unsigned*)&Bs[buf][s2 * 8 + tg + 4][cb];
            }
#pragma unroll
            for (int mt = 0; mt < 4; mt++)
#pragma unroll
                for (int nt = 0; nt < 8; nt++) {
                    asm volatile(
                        "mma.sync.aligned.m16n8k16.row.col.f32.f16.f16.f32 "
                        "{%0,%1,%2,%3}, {%4,%5,%6,%7}, {%8,%9}, {%0,%1,%2,%3};\n"
                        : "+f"(acc[mt][nt][0]), "+f"(acc[mt][nt][1]),
                          "+f"(acc[mt][nt][2]), "+f"(acc[mt][nt][3])
                        : "r"(a[mt][0]), "r"(a[mt][1]), "r"(a[mt][2]), "r"(a[mt][3]),
                          "r"(b[nt][0]), "r"(b[nt][1]));
                }
        }
        __syncthreads();
    }

    const float rs = rsqrtf(1.f + 1e-5f);
#pragma unroll
    for (int mt = 0; mt < 4; mt++) {
        int row0 = m0 + wm + mt * 16 + grp;
        int row1 = row0 + 8;
        int blx = row0 >> 5;
        int b = blx / L1, l = blx - b * L1;
        long hbase = (long)(b * L0 + l + d) * 32;
        int co0 = row0 & 31, co1 = row1 & 31;
        float sc0 = bng[co0] * rs, sh0 = bnb[co0];
        float sc1 = bng[co1] * rs, sh1 = bnb[co1];
#pragma unroll
        for (int nt = 0; nt < 8; nt++) {
            int col = n0 + wn + nt * 8 + tg * 2;
            half2 q0 = *(const half2*)&mm0[(long)row0 * 1024 + col];
            half2 q1 = *(const half2*)&mm0[(long)row1 * 1024 + col];
            float2 r0 = *(const float2*)&hold[(hbase + co0) * 1024 + col];
            float2 r1 = *(const float2*)&hold[(hbase + co1) * 1024 + col];
            float2 o0, o1;
            o0.x = (acc[mt][nt][0] + __half2float(q0.x) + r0.x) * sc0 + sh0;
            o0.y = (acc[mt][nt][1] + __half2float(q0.y) + r0.y) * sc0 + sh0;
            o1.x = (acc[mt][nt][2] + __half2float(q1.x) + r1.x) * sc1 + sh1;
            o1.y = (acc[mt][nt][3] + __half2float(q1.y) + r1.y) * sc1 + sh1;
            *(float2*)&hnew[(long)row0 * 1024 + col] = o0;
            *(float2*)&hnew[(long)row1 * 1024 + col] = o1;
        }
    }
}

// ---------------------------------------------------------------------------
// generic fp16 GEMM, ldmatrix A, 2-stage. flags:
// bit1: +bias[row], relu. bit2: C k-packed half. bit3: C plain half.
// bit4: end2 mode — +bias, NO relu, store only rows<12 fp32 to out[b][o][n].
// else: C fp32.
// ---------------------------------------------------------------------------
__global__ __launch_bounds__(256) void k_gemm_f16(const __half* __restrict__ A,
                                                  const half2* __restrict__ Bpk,
                                                  void* __restrict__ Cv,
                                                  int K, int lda, long ldb2, long ldc,
                                                  const float* __restrict__ bias,
                                                  int flags) {
    __shared__ __half As[2][128][40];
    __shared__ half2  Bs[2][16][264];
    int tid = threadIdx.x;
    int m0 = blockIdx.y * 128;
    long n0 = (long)blockIdx.x * 256;
    int w = tid >> 5, lane = tid & 31;
    int grp = lane >> 2, tg = lane & 3;
    int wm = (w & 1) * 64, wn = (w >> 1) * 64;
    int arow = lane & 15, akoff = (lane >> 4) * 8;
    unsigned asBase = (unsigned)__cvta_generic_to_shared(&As[0][0][0]);

    float acc[4][8][4];
#pragma unroll
    for (int mt = 0; mt < 4; mt++)
#pragma unroll
        for (int nt = 0; nt < 8; nt++)
#pragma unroll
            for (int c = 0; c < 4; c++) acc[mt][nt][c] = 0.f;

    int nstage = K / 32;
    {
#pragma unroll
        for (int i = 0; i < 2; i++) {
            int ch = tid + i * 256;
            int r = ch >> 2, p = (ch & 3) * 8;
            cp16(&As[0][r][p], A + (long)(m0 + r) * lda + p);
        }
#pragma unroll
        for (int i = 0; i < 4; i++) {
            int ch = tid + i * 256;
            int r = ch >> 6, c4 = (ch & 63) * 4;
            cp16(&Bs[0][r][c4], Bpk + (long)r * ldb2 + n0 + c4);
        }
        asm volatile("cp.async.commit_group;\n");
    }

    for (int s = 0; s < nstage; s++) {
        int buf = s & 1;
        if (s + 1 < nstage) {
            int nb = buf ^ 1;
            int k0 = (s + 1) * 32;
#pragma unroll
            for (int i = 0; i < 2; i++) {
                int ch = tid + i * 256;
                int r = ch >> 2, p = (ch & 3) * 8;
                cp16(&As[nb][r][p], A + (long)(m0 + r) * lda + k0 + p);
            }
#pragma unroll
            for (int i = 0; i < 4; i++) {
                int ch = tid + i * 256;
                int r = ch >> 6, c4 = (ch & 63) * 4;
                cp16(&Bs[nb][r][c4], Bpk + (long)(k0 / 2 + r) * ldb2 + n0 + c4);
            }
            asm volatile("cp.async.commit_group;\n");
            asm volatile("cp.async.wait_group 1;\n");
        } else {
            asm volatile("cp.async.wait_group 0;\n");
        }
        __syncthreads();

#pragma unroll
        for (int s2 = 0; s2 < 2; s2++) {
            unsigned a[4][4];
#pragma unroll
            for (int mt = 0; mt < 4; mt++) {
                unsigned addr = asBase +
                    (unsigned)(((buf << 7) + wm + mt * 16 + arow) * 40 +
                               s2 * 16 + akoff) * 2;
                asm volatile(
                    "ldmatrix.sync.aligned.m8n8.x4.shared.b16 {%0,%1,%2,%3}, [%4];\n"
                    : "=r"(a[mt][0]), "=r"(a[mt][1]), "=r"(a[mt][2]), "=r"(a[mt][3])
                    : "r"(addr));
            }
            unsigned b[8][2];
#pragma unroll
            for (int nt = 0; nt < 8; nt++) {
                int cb = wn + nt * 8 + grp;
                b[nt][0] = *(const unsigned*)&Bs[buf][s2 * 8 + tg][cb];
                b[nt][1] = *(const unsigned*)&Bs[buf][s2 * 8 + tg + 4][cb];
            }
#pragma unroll
            for (int mt = 0; mt < 4; mt++)
#pragma unroll
                for (int nt = 0; nt < 8; nt++) {
                    asm volatile(
                        "mma.sync.aligned.m16n8k16.row.col.f32.f16.f16.f32 "
                        "{%0,%1,%2,%3}, {%4,%5,%6,%7}, {%8,%9}, {%0,%1,%2,%3};\n"
                        : "+f"(acc[mt][nt][0]), "+f"(acc[mt][nt][1]),
                          "+f"(acc[mt][nt][2]), "+f"(acc[mt][nt][3])
                        : "r"(a[mt][0]), "r"(a[mt][1]), "r"(a[mt][2]), "r"(a[mt][3]),
                          "r"(b[nt][0]), "r"(b[nt][1]));
                }
        }
        __syncthreads();
    }

    float* Cf = (float*)Cv;
    __half* Ch = (__half*)Cv;
#pragma unroll
    for (int mt = 0; mt < 4; mt++) {
        int row0 = m0 + wm + mt * 16 + grp;
        int row1 = row0 + 8;
        float b0 = 0.f, b1 = 0.f;
        if (flags & (2 | 16)) { b0 = bias[row0]; b1 = bias[row1]; }
#pragma unroll
        for (int nt = 0; nt < 8; nt++) {
            long col = n0 + wn + nt * 8 + tg * 2;
            float v00 = acc[mt][nt][0], v01 = acc[mt][nt][1];
            float v10 = acc[mt][nt][2], v11 = acc[mt][nt][3];
            if (flags & 2) {
                v00 = fmaxf(v00 + b0, 0.f); v01 = fmaxf(v01 + b0, 0.f);
                v10 = fmaxf(v10 + b1, 0.f); v11 = fmaxf(v11 + b1, 0.f);
            } else if (flags & 16) {
                v00 += b0; v01 += b0; v10 += b1; v11 += b1;
            }
            if (flags & 16) {
                long bidx = col >> 10;
                long n = col & 1023;
                if (row0 < 12)
                    *(float2*)(Cf + (bidx * 12 + row0) * 1024 + n) =
                        make_float2(v00, v01);
                if (row1 < 12)
                    *(float2*)(Cf + (bidx * 12 + row1) * 1024 + n) =
                        make_float2(v10, v11);
            } else if (flags & 4) {
                long p0 = ((long)(row0 >> 1) * ldc + col) * 2 + (row0 & 1);
                long p1 = ((long)(row1 >> 1) * ldc + col) * 2 + (row1 & 1);
                Ch[p0] = __float2half(v00); Ch[p0 + 2] = __float2half(v01);
                Ch[p1] = __float2half(v10); Ch[p1 + 2] = __float2half(v11);
            } else if (flags & 8) {
                *(half2*)(Ch + (long)row0 * ldc + col) = __floats2half2_rn(v00, v01);
                *(half2*)(Ch + (long)row1 * ldc + col) = __floats2half2_rn(v10, v11);
            } else {
                *(float2*)(Cf + (long)row0 * ldc + col) = make_float2(v00, v01);
                *(float2*)(Cf + (long)row1 * ldc + col) = make_float2(v10, v11);
            }
        }
    }
}

// ---------------------------------------------------------------------------
__global__ __launch_bounds__(256) void k_prep(const float* __restrict__ skw,
                                              const float* __restrict__ skb,
                                              __half* __restrict__ wcat,
                                              float* __restrict__ bsum) {
    int co = blockIdx.x, k = threadIdx.x;
    int i = k >> 5, ci = k & 31;
    wcat[co * 256 + k] = __float2half(skw[((long)i * 256 + co) * 32 + ci]);
    if (k == 0) {
        float s = 0.f;
#pragma unroll
        for (int j = 0; j < 8; j++) s += skb[j * 256 + co];
        bsum[co] = s;
    }
}
__global__ __launch_bounds__(256) void k_roundh(const float* __restrict__ w,
                                                __half* __restrict__ o) {
    int i = blockIdx.x * 256 + threadIdx.x;
    o[i] = __float2half(w[i]);
}
// pad end2 weights to 128 rows (half) + padded bias
__global__ __launch_bounds__(256) void k_prep2(const float* __restrict__ w2,
                                               const float* __restrict__ b2,
                                               __half* __restrict__ w2p,
                                               float* __restrict__ b2p) {
    int o = blockIdx.x;
    int tid = threadIdx.x;
#pragma unroll
    for (int i = 0; i < 2; i++) {
        int k = tid + i * 256;
        w2p[o * 512 + k] = (o < 12) ? __float2half(w2[o * 512 + k]) : __float2half(0.f);
    }
    if (tid == 0) b2p[o] = (o < 12) ? b2[o] : 0.f;
}

// ---------------------------------------------------------------------------
extern "C" void kernel_launch(void* const* d_in, const int* in_sizes, int n_in,
                              void* d_out, int out_size) {
    const float* x        = (const float*)d_in[0];
    const float* start_w  = (const float*)d_in[1];
    const float* start_b  = (const float*)d_in[2];
    const float* nodevec1 = (const float*)d_in[3];
    const float* nodevec2 = (const float*)d_in[4];
    const float* filter_w = (const float*)d_in[5];
    const float* filter_b = (const float*)d_in[6];
    const float* gate_w   = (const float*)d_in[7];
    const float* gate_b   = (const float*)d_in[8];
    const float* skip_w   = (const float*)d_in[9];
    const float* skip_b   = (const float*)d_in[10];
    const float* gc_w     = (const float*)d_in[11];
    const float* gc_b     = (const float*)d_in[12];
    const float* bn_g     = (const float*)d_in[13];
    const float* bn_b     = (const float*)d_in[14];
    const float* end1_w   = (const float*)d_in[15];
    const float* end1_b   = (const float*)d_in[16];
    const float* end2_w   = (const float*)d_in[17];
    const float* end2_b   = (const float*)d_in[18];

    float *hA, *hB, *adpf, *bsk, *b2p;
    __half *mmA, *mm0, *Bm, *msk, *skip, *e1, *w1r, *wsk, *w2p;
    cudaGetSymbolAddress((void**)&hA, g_hA);
    cudaGetSymbolAddress((void**)&hB, g_hB);
    cudaGetSymbolAddress((void**)&mmA, g_mmA);
    cudaGetSymbolAddress((void**)&mm0, g_mm0);
    cudaGetSymbolAddress((void**)&adpf, g_adpf);
    cudaGetSymbolAddress((void**)&Bm, g_Bm);
    cudaGetSymbolAddress((void**)&msk, g_msk);
    cudaGetSymbolAddress((void**)&skip, g_skip);
    cudaGetSymbolAddress((void**)&e1, g_e1);
    cudaGetSymbolAddress((void**)&w1r, g_w1r);
    cudaGetSymbolAddress((void**)&wsk, g_wsk);
    cudaGetSymbolAddress((void**)&bsk, g_bsk);
    cudaGetSymbolAddress((void**)&w2p, g_w2p);
    cudaGetSymbolAddress((void**)&b2p, g_b2p);

    k_adp<<<1024, 256>>>(nodevec1, nodevec2, adpf, Bm);
    k_sgemm<<<dim3(8, 8), 256>>>(adpf, adpf, Bm);
    k_start<<<dim3(64 * 13, 4), 256>>>(x, start_w, start_b, hA);
    k_roundh<<<512, 256>>>(end1_w, w1r);
    k_prep<<<256, 256>>>(skip_w, skip_b, wsk, bsk);
    k_prep2<<<128, 256>>>(end2_w, end2_b, w2p, b2p);

    const int lens[9] = {13, 12, 10, 9, 7, 6, 4, 3, 1};
    const int dil[8]  = {1, 2, 1, 2, 1, 2, 1, 2};
    float* hcur = hA;
    float* hnext = hB;

    for (int i = 0; i < 8; i++) {
        int L0 = lens[i], L1 = lens[i + 1], d = dil[i];
        int doPre = (i < 7) ? 1 : 0;
        k_dconv<<<dim3(64 * L1, 16), 256>>>(hcur,
                                            filter_w + i * 2048, filter_b + i * 32,
                                            gate_w + i * 2048, gate_b + i * 32,
                                            gc_w + i * 32 * 96, gc_b + i * 32,
                                            mmA, mm0, msk, L0, L1, d, i, doPre);
        if (i < 7) {
            int M = 2048 * L1;
            k_gemm_gc<<<dim3(4, M / 128), 256>>>(
                mmA, (const half2*)Bm, hnext, hcur, mm0,
                bn_g + i * 32, bn_b + i * 32, L0, L1, d);
            float* t = hcur; hcur = hnext; hnext = t;
        }
    }

    // skip = relu(Wcat @ msk + bsum), k-packed half
    k_gemm_f16<<<dim3(65536 / 256, 2), 256>>>(
        wsk, (const half2*)msk, skip, 256, 256, 65536, 65536, bsk, 2 | 4);
    // e1 = relu(W1 @ skip + b1), k-packed half (B operand for end2 GEMM)
    k_gemm_f16<<<dim3(65536 / 256, 4), 256>>>(
        w1r, (const half2*)skip, e1, 256, 256, 65536, 65536, end1_b, 2 | 4);
    // out = W2 @ e1 + b2  (padded M=128, rows<12 stored with [b][o][n] mapping)
    k_gemm_f16<<<dim3(65536 / 256, 1), 256>>>(
        w2p, (const half2*)e1, (float*)d_out, 512, 512, 65536, 0, b2p, 16);
}

// round 15
// speedup vs baseline: 1.3377x; 1.0064x over previous
#include <cuda_runtime.h>
#include <cuda_fp16.h>
#include <math.h>
#include <stdint.h>

// ---------------------------------------------------------------------------
// GWNet2: B=64, N=1024, L=13, RC=DC=32, SC=256, EC=512, OUT=12, LAYERS=8
// h layout: [B][L][C][N] fp32.  (R14 base + fast exp-form activations)
// dconv: fp32x2 FMA (co-pair accumulators), gc premix fused.
// GEMMs: mma.sync m16n8k16 f16/f32acc, 2-stage cp.async, ldmatrix A frags,
// B operands k-packed half2. gc tail fused in x12-GEMM epilogue.
// end2 = padded tensor-core GEMM.
// ---------------------------------------------------------------------------

__device__ float  g_hA  [64 * 13 * 32 * 1024];
__device__ float  g_hB  [64 * 12 * 32 * 1024];
__device__ __half g_mmA [64 * 12 * 32 * 2048];       // [mm1 | mm2], A operand
__device__ __half g_mm0 [64 * 12 * 32 * 1024];       // Wm@m + gcb
__device__ float  g_adpf[1024 * 1024];               // ADP fp32 (for ADP^2)
__device__ __half g_Bm  [2048 * 1024];               // k-packed [ADP ; ADP^2]
__device__ __half g_msk [256 * 65536];               // k-packed concat m_last
__device__ __half g_skip[256 * 65536];               // k-packed relu(skip)
__device__ __half g_e1  [512 * 65536];               // k-packed relu(e1)
__device__ __half g_w1r [512 * 256];
__device__ __half g_wsk [256 * 256];
__device__ float  g_bsk [256];
__device__ __half g_w2p [128 * 512];                 // padded end2 weights
__device__ float  g_b2p [128];

// ---------------------------------------------------------------------------
__device__ __forceinline__ void cp16(void* smem, const void* g) {
    unsigned s = (unsigned)__cvta_generic_to_shared(smem);
    asm volatile("cp.async.cg.shared.global [%0], [%1], 16;\n" :: "r"(s), "l"(g));
}
__device__ __forceinline__ unsigned long long packf2(float lo, float hi) {
    unsigned long long r;
    asm("mov.b64 %0, {%1, %2};" : "=l"(r) : "f"(lo), "f"(hi));
    return r;
}
__device__ __forceinline__ void unpackf2(unsigned long long v, float& lo, float& hi) {
    asm("mov.b64 {%0, %1}, %2;" : "=f"(lo), "=f"(hi) : "l"(v));
}
#define FMA2(acc, a, b) \
    asm("fma.rn.f32x2 %0, %1, %2, %0;" : "+l"(acc) : "l"(a), "l"(b))

// fast gated activation: tanh(f) * sigmoid(g), exp-form (~1e-6 rel err)
__device__ __forceinline__ float gated_act(float f, float g) {
    float ef = __expf(2.f * f);
    float th = __fdividef(ef - 1.f, ef + 1.f);
    float sg = __fdividef(1.f, 1.f + __expf(-g));
    return th * sg;
}

// ---------------------------------------------------------------------------
// adp = softmax(relu(nv1 @ nv2)) -> fp32 adpf + k-packed half rows 0..511
// ---------------------------------------------------------------------------
__global__ __launch_bounds__(256) void k_adp(const float* __restrict__ nv1,
                                             const float* __restrict__ nv2,
                                             float* __restrict__ adpf,
                                             __half* __restrict__ Bpk) {
    __shared__ float red[256];
    int v = blockIdx.x, tid = threadIdx.x;
    float n1[10];
#pragma unroll
    for (int k = 0; k < 10; k++) n1[k] = nv1[v * 10 + k];
    float a[4];
#pragma unroll
    for (int j = 0; j < 4; j++) {
        int w = tid + j * 256;
        float s = 0.f;
#pragma unroll
        for (int k = 0; k < 10; k++) s += n1[k] * nv2[k * 1024 + w];
        a[j] = fmaxf(s, 0.f);
    }
    float mx = fmaxf(fmaxf(a[0], a[1]), fmaxf(a[2], a[3]));
    red[tid] = mx; __syncthreads();
    for (int s = 128; s > 0; s >>= 1) {
        if (tid < s) red[tid] = fmaxf(red[tid], red[tid + s]);
        __syncthreads();
    }
    mx = red[0]; __syncthreads();
    float e[4]; float sum = 0.f;
#pragma unroll
    for (int j = 0; j < 4; j++) { e[j] = expf(a[j] - mx); sum += e[j]; }
    red[tid] = sum; __syncthreads();
    for (int s = 128; s > 0; s >>= 1) {
        if (tid < s) red[tid] += red[tid + s];
        __syncthreads();
    }
    float inv = 1.f / red[0];
#pragma unroll
    for (int j = 0; j < 4; j++) {
        int w = tid + j * 256;
        float val = e[j] * inv;
        adpf[(long)v * 1024 + w] = val;
        Bpk[((long)(v >> 1) * 1024 + w) * 2 + (v & 1)] = __float2half(val);
    }
}

// ---------------------------------------------------------------------------
__global__ __launch_bounds__(256) void k_start(const float* __restrict__ x,
                                               const float* __restrict__ sw,
                                               const float* __restrict__ sb,
                                               float* __restrict__ h) {
    int bl = blockIdx.x;
    int b = bl / 13, l = bl - b * 13;
    int n = blockIdx.y * 256 + threadIdx.x;
    float x0 = x[(((long)b * 2 + 0) * 1024 + n) * 13 + l];
    float x1 = x[(((long)b * 2 + 1) * 1024 + n) * 13 + l];
    float* hb = h + ((long)(b * 13 + l) * 32) * 1024 + n;
#pragma unroll
    for (int c = 0; c < 32; c++)
        hb[(long)c * 1024] = sw[c * 2] * x0 + sw[c * 2 + 1] * x1 + sb[c];
}

// ---------------------------------------------------------------------------
// dilated conv + gated activation + gc channel premix, packed fp32x2 FMA.
// ---------------------------------------------------------------------------
__global__ __launch_bounds__(256) void k_dconv(const float* __restrict__ h,
                                               const float* __restrict__ fw,
                                               const float* __restrict__ fb,
                                               const float* __restrict__ gw,
                                               const float* __restrict__ gb,
                                               const float* __restrict__ gcw,
                                               const float* __restrict__ gcb,
                                               __half* __restrict__ mmA,
                                               __half* __restrict__ mm0,
                                               __half* __restrict__ msk,
                                               int L0, int L1, int d, int layer,
                                               int doPre) {
    __shared__ float  s_in[2][32][64];
    __shared__ float4 s_wf[32][16];
    __shared__ float4 s_wg[32][16];
    __shared__ float4 s_wpA[32][16];
    __shared__ float2 s_wpB[32][16];
    __shared__ unsigned long long s_fbp[16], s_gbp[16], s_gcbp[16];

    int bl = blockIdx.x;
    int b = bl / L1, l = bl - b * L1;
    int n0 = blockIdx.y * 64;
    int tid = threadIdx.x;

    for (int idx = tid; idx < 512; idx += 256) {
        int ci = idx >> 4, p = idx & 15;
        int co0 = p * 2, co1 = p * 2 + 1;
        int o0 = (co0 * 32 + ci) * 2, o1 = (co1 * 32 + ci) * 2;
        s_wf[ci][p] = make_float4(fw[o0], fw[o1], fw[o0 + 1], fw[o1 + 1]);
        s_wg[ci][p] = make_float4(gw[o0], gw[o1], gw[o0 + 1], gw[o1 + 1]);
        if (doPre) {
            s_wpA[ci][p] = make_float4(gcw[co0 * 96 + ci], gcw[co1 * 96 + ci],
                                       gcw[co0 * 96 + 32 + ci], gcw[co1 * 96 + 32 + ci]);
            s_wpB[ci][p] = make_float2(gcw[co0 * 96 + 64 + ci], gcw[co1 * 96 + 64 + ci]);
        }
    }
    if (tid < 16) {
        s_fbp[tid] = packf2(fb[2 * tid], fb[2 * tid + 1]);
        s_gbp[tid] = packf2(gb[2 * tid], gb[2 * tid + 1]);
        s_gcbp[tid] = doPre ? packf2(gcb[2 * tid], gcb[2 * tid + 1]) : 0ull;
    }
    const float* hb = h + ((long)(b * L0 + l) * 32) * 1024 + n0;
    for (int idx = tid; idx < 4096; idx += 256) {
        int tap = idx >> 11, ci = (idx >> 6) & 31, nl = idx & 63;
        s_in[tap][ci][nl] = hb[((long)(tap * d) * 32 + ci) * 1024 + nl];
    }
    __syncthreads();

    int nl = tid & 63, cg = tid >> 6;
    unsigned long long fa2[4], ga2[4];
#pragma unroll
    for (int p = 0; p < 4; p++) { fa2[p] = s_fbp[cg * 4 + p]; ga2[p] = s_gbp[cg * 4 + p]; }
#pragma unroll
    for (int ci = 0; ci < 32; ci++) {
        float v0 = s_in[0][ci][nl], v1 = s_in[1][ci][nl];
        unsigned long long vv0 = packf2(v0, v0), vv1 = packf2(v1, v1);
#pragma unroll
        for (int p = 0; p < 4; p++) {
            ulonglong2 wf = *(const ulonglong2*)&s_wf[ci][cg * 4 + p];
            FMA2(fa2[p], wf.x, vv0);
            FMA2(fa2[p], wf.y, vv1);
            ulonglong2 wg = *(const ulonglong2*)&s_wg[ci][cg * 4 + p];
            FMA2(ga2[p], wg.x, vv0);
            FMA2(ga2[p], wg.y, vv1);
        }
    }

    bool last = (l == L1 - 1);
    long col = (long)b * 1024 + n0 + nl;
    float mval[8];
#pragma unroll
    for (int p = 0; p < 4; p++) {
        float flo, fhi, glo, ghi;
        unpackf2(fa2[p], flo, fhi);
        unpackf2(ga2[p], glo, ghi);
        mval[2 * p]     = gated_act(flo, glo);
        mval[2 * p + 1] = gated_act(fhi, ghi);
    }
#pragma unroll
    for (int u = 0; u < 8; u++) {
        if (last) {
            int k = layer * 32 + cg * 8 + u;
            msk[((long)(k >> 1) * 65536 + col) * 2 + (k & 1)] = __float2half(mval[u]);
        }
    }
    if (!doPre) return;

    __syncthreads();
    float (*s_m)[64] = s_in[0];
#pragma unroll
    for (int u = 0; u < 8; u++) s_m[cg * 8 + u][nl] = mval[u];
    __syncthreads();

    unsigned long long p02[4], p12[4], p22[4];
#pragma unroll
    for (int p = 0; p < 4; p++) { p02[p] = s_gcbp[cg * 4 + p]; p12[p] = 0ull; p22[p] = 0ull; }
#pragma unroll
    for (int ci = 0; ci < 32; ci++) {
        float v = s_m[ci][nl];
        unsigned long long vv = packf2(v, v);
#pragma unroll
        for (int p = 0; p < 4; p++) {
            ulonglong2 wa = *(const ulonglong2*)&s_wpA[ci][cg * 4 + p];
            FMA2(p02[p], wa.x, vv);
            FMA2(p12[p], wa.y, vv);
            unsigned long long wb = *(const unsigned long long*)&s_wpB[ci][cg * 4 + p];
            FMA2(p22[p], wb, vv);
        }
    }
    long rowbase = (long)(b * L1 + l) * 32;
#pragma unroll
    for (int p = 0; p < 4; p++) {
        float a0, a1, b0, b1, c0, c1;
        unpackf2(p02[p], a0, a1);
        unpackf2(p12[p], b0, b1);
        unpackf2(p22[p], c0, c1);
        long r0 = rowbase + cg * 8 + 2 * p;
        long r1 = r0 + 1;
        mm0[r0 * 1024 + n0 + nl] = __float2half(a0);
        mm0[r1 * 1024 + n0 + nl] = __float2half(a1);
        mmA[r0 * 2048 + n0 + nl] = __float2half(b0);
        mmA[r1 * 2048 + n0 + nl] = __float2half(b1);
        mmA[r0 * 2048 + 1024 + n0 + nl] = __float2half(c0);
        mmA[r1 * 2048 + 1024 + n0 + nl] = __float2half(c1);
    }
}

// ---------------------------------------------------------------------------
// fp32 SIMT SGEMM: ADP^2 = ADP @ ADP; k-packed half into Bpk rows 512..1023
// ---------------------------------------------------------------------------
__global__ __launch_bounds__(256) void k_sgemm(const float* __restrict__ A,
                                               const float* __restrict__ B,
                                               __half* __restrict__ Bpk) {
    __shared__ float As[16][132];
    __shared__ float Bs[16][128];
    int tid = threadIdx.x;
    int m0 = blockIdx.y * 128, n0 = blockIdx.x * 128;
    int ty = tid >> 4, tx = tid & 15;
    float acc[8][8];
#pragma unroll
    for (int i = 0; i < 8; i++)
#pragma unroll
        for (int j = 0; j < 8; j++) acc[i][j] = 0.f;

    for (int k0 = 0; k0 < 1024; k0 += 16) {
#pragma unroll
        for (int i = 0; i < 2; i++) {
            int f = tid + i * 256;
            int r = f >> 2, kc = (f & 3) * 4;
            float4 v = *(const float4*)(A + (long)(m0 + r) * 1024 + k0 + kc);
            As[kc + 0][r] = v.x; As[kc + 1][r] = v.y;
            As[kc + 2][r] = v.z; As[kc + 3][r] = v.w;
        }
#pragma unroll
        for (int i = 0; i < 2; i++) {
            int f = tid + i * 256;
            int r = f >> 5, nc = (f & 31) * 4;
            float4 v = *(const float4*)(B + (long)(k0 + r) * 1024 + n0 + nc);
            *(float4*)&Bs[r][nc] = v;
        }
        __syncthreads();
#pragma unroll
        for (int k = 0; k < 16; k++) {
            float a[8], b[8];
            float4 a0 = *(const float4*)&As[k][ty * 8];
            float4 a1 = *(const float4*)&As[k][ty * 8 + 4];
            a[0] = a0.x; a[1] = a0.y; a[2] = a0.z; a[3] = a0.w;
            a[4] = a1.x; a[5] = a1.y; a[6] = a1.z; a[7] = a1.w;
            float4 b0 = *(const float4*)&Bs[k][tx * 8];
            float4 b1 = *(const float4*)&Bs[k][tx * 8 + 4];
            b[0] = b0.x; b[1] = b0.y; b[2] = b0.z; b[3] = b0.w;
            b[4] = b1.x; b[5] = b1.y; b[6] = b1.z; b[7] = b1.w;
#pragma unroll
            for (int i = 0; i < 8; i++)
#pragma unroll
                for (int j = 0; j < 8; j++) acc[i][j] += a[i] * b[j];
        }
        __syncthreads();
    }
#pragma unroll
    for (int i = 0; i < 8; i++) {
        int v = m0 + ty * 8 + i;
#pragma unroll
        for (int j = 0; j < 8; j++) {
            int w = n0 + tx * 8 + j;
            Bpk[((long)(512 + (v >> 1)) * 1024 + w) * 2 + (v & 1)] =
                __float2half(acc[i][j]);
        }
    }
}

// ---------------------------------------------------------------------------
// fused layer GEMM + gc tail (2-stage cp.async, ldmatrix A).
// ---------------------------------------------------------------------------
__global__ __launch_bounds__(256) void k_gemm_gc(const __half* __restrict__ A,
                                                 const half2* __restrict__ Bpk,
                                                 float* __restrict__ hnew,
                                                 const float* __restrict__ hold,
                                                 const __half* __restrict__ mm0,
                                                 const float* __restrict__ bng,
                                                 const float* __restrict__ bnb,
                                                 int L0, int L1, int d) {
    __shared__ __half As[2][128][40];
    __shared__ half2  Bs[2][16][264];
    int tid = threadIdx.x;
    int m0 = blockIdx.y * 128;
    int n0 = blockIdx.x * 256;
    int w = tid >> 5, lane = tid & 31;
    int grp = lane >> 2, tg = lane & 3;
    int wm = (w & 1) * 64, wn = (w >> 1) * 64;
    int arow = lane & 15, akoff = (lane >> 4) * 8;
    unsigned asBase = (unsigned)__cvta_generic_to_shared(&As[0][0][0]);

    float acc[4][8][4];
#pragma unroll
    for (int mt = 0; mt < 4; mt++)
#pragma unroll
        for (int nt = 0; nt < 8; nt++)
#pragma unroll
            for (int c = 0; c < 4; c++) acc[mt][nt][c] = 0.f;

    const int nstage = 2048 / 32;
    {
#pragma unroll
        for (int i = 0; i < 2; i++) {
            int ch = tid + i * 256;
            int r = ch >> 2, p = (ch & 3) * 8;
            cp16(&As[0][r][p], A + (long)(m0 + r) * 2048 + p);
        }
#pragma unroll
        for (int i = 0; i < 4; i++) {
            int ch = tid + i * 256;
            int r = ch >> 6, c4 = (ch & 63) * 4;
            cp16(&Bs[0][r][c4], Bpk + (long)r * 1024 + n0 + c4);
        }
        asm volatile("cp.async.commit_group;\n");
    }

    for (int s = 0; s < nstage; s++) {
        int buf = s & 1;
        if (s + 1 < nstage) {
            int nb = buf ^ 1;
            int k0 = (s + 1) * 32;
#pragma unroll
            for (int i = 0; i < 2; i++) {
                int ch = tid + i * 256;
                int r = ch >> 2, p = (ch & 3) * 8;
                cp16(&As[nb][r][p], A + (long)(m0 + r) * 2048 + k0 + p);
            }
#pragma unroll
            for (int i = 0; i < 4; i++) {
                int ch = tid + i * 256;
                int r = ch >> 6, c4 = (ch & 63) * 4;
                cp16(&Bs[nb][r][c4], Bpk + (long)(k0 / 2 + r) * 1024 + n0 + c4);
            }
            asm volatile("cp.async.commit_group;\n");
            asm volatile("cp.async.wait_group 1;\n");
        } else {
            asm volatile("cp.async.wait_group 0;\n");
        }
        __syncthreads();

#pragma unroll
        for (int s2 = 0; s2 < 2; s2++) {
            unsigned a[4][4];
#pragma unroll
            for (int mt = 0; mt < 4; mt++) {
                unsigned addr = asBase +
                    (unsigned)(((buf << 7) + wm + mt * 16 + arow) * 40 +
                               s2 * 16 + akoff) * 2;
                asm volatile(
                    "ldmatrix.sync.aligned.m8n8.x4.shared.b16 {%0,%1,%2,%3}, [%4];\n"
                    : "=r"(a[mt][0]), "=r"(a[mt][1]), "=r"(a[mt][2]), "=r"(a[mt][3])
                    : "r"(addr));
            }
            unsigned b[8][2];
#pragma unroll
            for (int nt = 0; nt < 8; nt++) {
                int cb = wn + nt * 8 + grp;
                b[nt][0] = *(const unsigned*)&Bs[buf][s2 * 8 + tg][cb];
                b[nt][1] = *(const unsigned*)&Bs[buf][s2 * 8 + tg + 4][cb];
            }
#pragma unroll
            for (int mt = 0; mt < 4; mt++)
#pragma unroll
                for (int nt = 0; nt < 8; nt++) {
                    asm volatile(
                        "mma.sync.aligned.m16n8k16.row.col.f32.f16.f16.f32 "
                        "{%0,%1,%2,%3}, {%4,%5,%6,%7}, {%8,%9}, {%0,%1,%2,%3};\n"
                        : "+f"(acc[mt][nt][0]), "+f"(acc[mt][nt][1]),
                          "+f"(acc[mt][nt][2]), "+f"(acc[mt][nt][3])
                        : "r"(a[mt][0]), "r"(a[mt][1]), "r"(a[mt][2]), "r"(a[mt][3]),
                          "r"(b[nt][0]), "r"(b[nt][1]));
                }
        }
        __syncthreads();
    }

    const float rs = rsqrtf(1.f + 1e-5f);
#pragma unroll
    for (int mt = 0; mt < 4; mt++) {
        int row0 = m0 + wm + mt * 16 + grp;
        int row1 = row0 + 8;
        int blx = row0 >> 5;
        int b = blx / L1, l = blx - b * L1;
        long hbase = (long)(b * L0 + l + d) * 32;
        int co0 = row0 & 31, co1 = row1 & 31;
        float sc0 = bng[co0] * rs, sh0 = bnb[co0];
        float sc1 = bng[co1] * rs, sh1 = bnb[co1];
#pragma unroll
        for (int nt = 0; nt < 8; nt++) {
            int col = n0 + wn + nt * 8 + tg * 2;
            half2 q0 = *(const half2*)&mm0[(long)row0 * 1024 + col];
            half2 q1 = *(const half2*)&mm0[(long)row1 * 1024 + col];
            float2 r0 = *(const float2*)&hold[(hbase + co0) * 1024 + col];
            float2 r1 = *(const float2*)&hold[(hbase + co1) * 1024 + col];
            float2 o0, o1;
            o0.x = (acc[mt][nt][0] + __half2float(q0.x) + r0.x) * sc0 + sh0;
            o0.y = (acc[mt][nt][1] + __half2float(q0.y) + r0.y) * sc0 + sh0;
            o1.x = (acc[mt][nt][2] + __half2float(q1.x) + r1.x) * sc1 + sh1;
            o1.y = (acc[mt][nt][3] + __half2float(q1.y) + r1.y) * sc1 + sh1;
            *(float2*)&hnew[(long)row0 * 1024 + col] = o0;
            *(float2*)&hnew[(long)row1 * 1024 + col] = o1;
        }
    }
}

// ---------------------------------------------------------------------------
// generic fp16 GEMM, ldmatrix A, 2-stage. flags:
// bit1: +bias[row], relu. bit2: C k-packed half. bit3: C plain half.
// bit4: end2 mode — +bias, NO relu, store only rows<12 fp32 to out[b][o][n].
// else: C fp32.
// ---------------------------------------------------------------------------
__global__ __launch_bounds__(256) void k_gemm_f16(const __half* __restrict__ A,
                                                  const half2* __restrict__ Bpk,
                                                  void* __restrict__ Cv,
                                                  int K, int lda, long ldb2, long ldc,
                                                  const float* __restrict__ bias,
                                                  int flags) {
    __shared__ __half As[2][128][40];
    __shared__ half2  Bs[2][16][264];
    int tid = threadIdx.x;
    int m0 = blockIdx.y * 128;
    long n0 = (long)blockIdx.x * 256;
    int w = tid >> 5, lane = tid & 31;
    int grp = lane >> 2, tg = lane & 3;
    int wm = (w & 1) * 64, wn = (w >> 1) * 64;
    int arow = lane & 15, akoff = (lane >> 4) * 8;
    unsigned asBase = (unsigned)__cvta_generic_to_shared(&As[0][0][0]);

    float acc[4][8][4];
#pragma unroll
    for (int mt = 0; mt < 4; mt++)
#pragma unroll
        for (int nt = 0; nt < 8; nt++)
#pragma unroll
            for (int c = 0; c < 4; c++) acc[mt][nt][c] = 0.f;

    int nstage = K / 32;
    {
#pragma unroll
        for (int i = 0; i < 2; i++) {
            int ch = tid + i * 256;
            int r = ch >> 2, p = (ch & 3) * 8;
            cp16(&As[0][r][p], A + (long)(m0 + r) * lda + p);
        }
#pragma unroll
        for (int i = 0; i < 4; i++) {
            int ch = tid + i * 256;
            int r = ch >> 6, c4 = (ch & 63) * 4;
            cp16(&Bs[0][r][c4], Bpk + (long)r * ldb2 + n0 + c4);
        }
        asm volatile("cp.async.commit_group;\n");
    }

    for (int s = 0; s < nstage; s++) {
        int buf = s & 1;
        if (s + 1 < nstage) {
            int nb = buf ^ 1;
            int k0 = (s + 1) * 32;
#pragma unroll
            for (int i = 0; i < 2; i++) {
                int ch = tid + i * 256;
                int r = ch >> 2, p = (ch & 3) * 8;
                cp16(&As[nb][r][p], A + (long)(m0 + r) * lda + k0 + p);
            }
#pragma unroll
            for (int i = 0; i < 4; i++) {
                int ch = tid + i * 256;
                int r = ch >> 6, c4 = (ch & 63) * 4;
                cp16(&Bs[nb][r][c4], Bpk + (long)(k0 / 2 + r) * ldb2 + n0 + c4);
            }
            asm volatile("cp.async.commit_group;\n");
            asm volatile("cp.async.wait_group 1;\n");
        } else {
            asm volatile("cp.async.wait_group 0;\n");
        }
        __syncthreads();

#pragma unroll
        for (int s2 = 0; s2 < 2; s2++) {
            unsigned a[4][4];
#pragma unroll
            for (int mt = 0; mt < 4; mt++) {
                unsigned addr = asBase +
                    (unsigned)(((buf << 7) + wm + mt * 16 + arow) * 40 +
                               s2 * 16 + akoff) * 2;
                asm volatile(
                    "ldmatrix.sync.aligned.m8n8.x4.shared.b16 {%0,%1,%2,%3}, [%4];\n"
                    : "=r"(a[mt][0]), "=r"(a[mt][1]), "=r"(a[mt][2]), "=r"(a[mt][3])
                    : "r"(addr));
            }
            unsigned b[8][2];
#pragma unroll
            for (int nt = 0; nt < 8; nt++) {
                int cb = wn + nt * 8 + grp;
                b[nt][0] = *(const unsigned*)&Bs[buf][s2 * 8 + tg][cb];
                b[nt][1] = *(const unsigned*)&Bs[buf][s2 * 8 + tg + 4][cb];
            }
#pragma unroll
            for (int mt = 0; mt < 4; mt++)
#pragma unroll
                for (int nt = 0; nt < 8; nt++) {
                    asm volatile(
                        "mma.sync.aligned.m16n8k16.row.col.f32.f16.f16.f32 "
                        "{%0,%1,%2,%3}, {%4,%5,%6,%7}, {%8,%9}, {%0,%1,%2,%3};\n"
                        : "+f"(acc[mt][nt][0]), "+f"(acc[mt][nt][1]),
                          "+f"(acc[mt][nt][2]), "+f"(acc[mt][nt][3])
                        : "r"(a[mt][0]), "r"(a[mt][1]), "r"(a[mt][2]), "r"(a[mt][3]),
                          "r"(b[nt][0]), "r"(b[nt][1]));
                }
        }
        __syncthreads();
    }

    float* Cf = (float*)Cv;
    __half* Ch = (__half*)Cv;
#pragma unroll
    for (int mt = 0; mt < 4; mt++) {
        int row0 = m0 + wm + mt * 16 + grp;
        int row1 = row0 + 8;
        float b0 = 0.f, b1 = 0.f;
        if (flags & (2 | 16)) { b0 = bias[row0]; b1 = bias[row1]; }
#pragma unroll
        for (int nt = 0; nt < 8; nt++) {
            long col = n0 + wn + nt * 8 + tg * 2;
            float v00 = acc[mt][nt][0], v01 = acc[mt][nt][1];
            float v10 = acc[mt][nt][2], v11 = acc[mt][nt][3];
            if (flags & 2) {
                v00 = fmaxf(v00 + b0, 0.f); v01 = fmaxf(v01 + b0, 0.f);
                v10 = fmaxf(v10 + b1, 0.f); v11 = fmaxf(v11 + b1, 0.f);
            } else if (flags & 16) {
                v00 += b0; v01 += b0; v10 += b1; v11 += b1;
            }
            if (flags & 16) {
                long bidx = col >> 10;
                long n = col & 1023;
                if (row0 < 12)
                    *(float2*)(Cf + (bidx * 12 + row0) * 1024 + n) =
                        make_float2(v00, v01);
                if (row1 < 12)
                    *(float2*)(Cf + (bidx * 12 + row1) * 1024 + n) =
                        make_float2(v10, v11);
            } else if (flags & 4) {
                long p0 = ((long)(row0 >> 1) * ldc + col) * 2 + (row0 & 1);
                long p1 = ((long)(row1 >> 1) * ldc + col) * 2 + (row1 & 1);
                Ch[p0] = __float2half(v00); Ch[p0 + 2] = __float2half(v01);
                Ch[p1] = __float2half(v10); Ch[p1 + 2] = __float2half(v11);
            } else if (flags & 8) {
                *(half2*)(Ch + (long)row0 * ldc + col) = __floats2half2_rn(v00, v01);
                *(half2*)(Ch + (long)row1 * ldc + col) = __floats2half2_rn(v10, v11);
            } else {
                *(float2*)(Cf + (long)row0 * ldc + col) = make_float2(v00, v01);
                *(float2*)(Cf + (long)row1 * ldc + col) = make_float2(v10, v11);
            }
        }
    }
}

// ---------------------------------------------------------------------------
// merged prep: blocks [0,512) round end1_w; [512,768) skip wcat+bias;
// [768,896) pad end2 weights/bias.
// ---------------------------------------------------------------------------
__global__ __launch_bounds__(256) void k_prep_all(const float* __restrict__ end1_w,
                                                  const float* __restrict__ skw,
                                                  const float* __restrict__ skb,
                                                  const float* __restrict__ w2,
                                                  const float* __restrict__ b2,
                                                  __half* __restrict__ w1r,
                                                  __half* __restrict__ wcat,
                                                  float* __restrict__ bsum,
                                                  __half* __restrict__ w2p,
                                                  float* __restrict__ b2p) {
    int blk = blockIdx.x;
    int tid = threadIdx.x;
    if (blk < 512) {
        int i = blk * 256 + tid;
        w1r[i] = __float2half(end1_w[i]);
    } else if (blk < 768) {
        int co = blk - 512, k = tid;
        int i = k >> 5, ci = k & 31;
        wcat[co * 256 + k] = __float2half(skw[((long)i * 256 + co) * 32 + ci]);
        if (k == 0) {
            float s = 0.f;
#pragma unroll
            for (int j = 0; j < 8; j++) s += skb[j * 256 + co];
            bsum[co] = s;
        }
    } else {
        int o = blk - 768;
#pragma unroll
        for (int i = 0; i < 2; i++) {
            int k = tid + i * 256;
            w2p[o * 512 + k] = (o < 12) ? __float2half(w2[o * 512 + k])
                                        : __float2half(0.f);
        }
        if (tid == 0) b2p[o] = (o < 12) ? b2[o] : 0.f;
    }
}

// ---------------------------------------------------------------------------
extern "C" void kernel_launch(void* const* d_in, const int* in_sizes, int n_in,
                              void* d_out, int out_size) {
    const float* x        = (const float*)d_in[0];
    const float* start_w  = (const float*)d_in[1];
    const float* start_b  = (const float*)d_in[2];
    const float* nodevec1 = (const float*)d_in[3];
    const float* nodevec2 = (const float*)d_in[4];
    const float* filter_w = (const float*)d_in[5];
    const float* filter_b = (const float*)d_in[6];
    const float* gate_w   = (const float*)d_in[7];
    const float* gate_b   = (const float*)d_in[8];
    const float* skip_w   = (const float*)d_in[9];
    const float* skip_b   = (const float*)d_in[10];
    const float* gc_w     = (const float*)d_in[11];
    const float* gc_b     = (const float*)d_in[12];
    const float* bn_g     = (const float*)d_in[13];
    const float* bn_b     = (const float*)d_in[14];
    const float* end1_w   = (const float*)d_in[15];
    const float* end1_b   = (const float*)d_in[16];
    const float* end2_w   = (const float*)d_in[17];
    const float* end2_b   = (const float*)d_in[18];

    float *hA, *hB, *adpf, *bsk, *b2p;
    __half *mmA, *mm0, *Bm, *msk, *skip, *e1, *w1r, *wsk, *w2p;
    cudaGetSymbolAddress((void**)&hA, g_hA);
    cudaGetSymbolAddress((void**)&hB, g_hB);
    cudaGetSymbolAddress((void**)&mmA, g_mmA);
    cudaGetSymbolAddress((void**)&mm0, g_mm0);
    cudaGetSymbolAddress((void**)&adpf, g_adpf);
    cudaGetSymbolAddress((void**)&Bm, g_Bm);
    cudaGetSymbolAddress((void**)&msk, g_msk);
    cudaGetSymbolAddress((void**)&skip, g_skip);
    cudaGetSymbolAddress((void**)&e1, g_e1);
    cudaGetSymbolAddress((void**)&w1r, g_w1r);
    cudaGetSymbolAddress((void**)&wsk, g_wsk);
    cudaGetSymbolAddress((void**)&bsk, g_bsk);
    cudaGetSymbolAddress((void**)&w2p, g_w2p);
    cudaGetSymbolAddress((void**)&b2p, g_b2p);

    k_adp<<<1024, 256>>>(nodevec1, nodevec2, adpf, Bm);
    k_sgemm<<<dim3(8, 8), 256>>>(adpf, adpf, Bm);
    k_start<<<dim3(64 * 13, 4), 256>>>(x, start_w, start_b, hA);
    k_prep_all<<<896, 256>>>(end1_w, skip_w, skip_b, end2_w, end2_b,
                             w1r, wsk, bsk, w2p, b2p);

    const int lens[9] = {13, 12, 10, 9, 7, 6, 4, 3, 1};
    const int dil[8]  = {1, 2, 1, 2, 1, 2, 1, 2};
    float* hcur = hA;
    float* hnext = hB;

    for (int i = 0; i < 8; i++) {
        int L0 = lens[i], L1 = lens[i + 1], d = dil[i];
        int doPre = (i < 7) ? 1 : 0;
        k_dconv<<<dim3(64 * L1, 16), 256>>>(hcur,
                                            filter_w + i * 2048, filter_b + i * 32,
                                            gate_w + i * 2048, gate_b + i * 32,
                                            gc_w + i * 32 * 96, gc_b + i * 32,
                                            mmA, mm0, msk, L0, L1, d, i, doPre);
        if (i < 7) {
            int M = 2048 * L1;
            k_gemm_gc<<<dim3(4, M / 128), 256>>>(
                mmA, (const half2*)Bm, hnext, hcur, mm0,
                bn_g + i * 32, bn_b + i * 32, L0, L1, d);
            float* t = hcur; hcur = hnext; hnext = t;
        }
    }

    // skip = relu(Wcat @ msk + bsum), k-packed half
    k_gemm_f16<<<dim3(65536 / 256, 2), 256>>>(
        wsk, (const half2*)msk, skip, 256, 256, 65536, 65536, bsk, 2 | 4);
    // e1 = relu(W1 @ skip + b1), k-packed half (B operand for end2 GEMM)
    k_gemm_f16<<<dim3(65536 / 256, 4), 256>>>(
        w1r, (const half2*)skip, e1, 256, 256, 65536, 65536, end1_b, 2 | 4);
    // out = W2 @ e1 + b2  (padded M=128, rows<12 stored with [b][o][n] mapping)
    k_gemm_f16<<<dim3(65536 / 256, 1), 256>>>(
        w2p, (const half2*)e1, (float*)d_out, 512, 512, 65536, 0, b2p, 16);
}

// round 16
// speedup vs baseline: 1.3448x; 1.0053x over previous
#include <cuda_runtime.h>
#include <cuda_fp16.h>
#include <math.h>
#include <stdint.h>

// ---------------------------------------------------------------------------
// GWNet2: B=64, N=1024, L=13, RC=DC=32, SC=256, EC=512, OUT=12, LAYERS=8
// h layout: [B][L][C][N] fp32.  (R15 base + BN=128 GEMM variant for small-M layers)
// ---------------------------------------------------------------------------

__device__ float  g_hA  [64 * 13 * 32 * 1024];
__device__ float  g_hB  [64 * 12 * 32 * 1024];
__device__ __half g_mmA [64 * 12 * 32 * 2048];       // [mm1 | mm2], A operand
__device__ __half g_mm0 [64 * 12 * 32 * 1024];       // Wm@m + gcb
__device__ float  g_adpf[1024 * 1024];               // ADP fp32 (for ADP^2)
__device__ __half g_Bm  [2048 * 1024];               // k-packed [ADP ; ADP^2]
__device__ __half g_msk [256 * 65536];               // k-packed concat m_last
__device__ __half g_skip[256 * 65536];               // k-packed relu(skip)
__device__ __half g_e1  [512 * 65536];               // k-packed relu(e1)
__device__ __half g_w1r [512 * 256];
__device__ __half g_wsk [256 * 256];
__device__ float  g_bsk [256];
__device__ __half g_w2p [128 * 512];                 // padded end2 weights
__device__ float  g_b2p [128];

// ---------------------------------------------------------------------------
__device__ __forceinline__ void cp16(void* smem, const void* g) {
    unsigned s = (unsigned)__cvta_generic_to_shared(smem);
    asm volatile("cp.async.cg.shared.global [%0], [%1], 16;\n" :: "r"(s), "l"(g));
}
__device__ __forceinline__ unsigned long long packf2(float lo, float hi) {
    unsigned long long r;
    asm("mov.b64 %0, {%1, %2};" : "=l"(r) : "f"(lo), "f"(hi));
    return r;
}
__device__ __forceinline__ void unpackf2(unsigned long long v, float& lo, float& hi) {
    asm("mov.b64 {%0, %1}, %2;" : "=f"(lo), "=f"(hi) : "l"(v));
}
#define FMA2(acc, a, b) \
    asm("fma.rn.f32x2 %0, %1, %2, %0;" : "+l"(acc) : "l"(a), "l"(b))

__device__ __forceinline__ float gated_act(float f, float g) {
    float ef = __expf(2.f * f);
    float th = __fdividef(ef - 1.f, ef + 1.f);
    float sg = __fdividef(1.f, 1.f + __expf(-g));
    return th * sg;
}

// ---------------------------------------------------------------------------
__global__ __launch_bounds__(256) void k_adp(const float* __restrict__ nv1,
                                             const float* __restrict__ nv2,
                                             float* __restrict__ adpf,
                                             __half* __restrict__ Bpk) {
    __shared__ float red[256];
    int v = blockIdx.x, tid = threadIdx.x;
    float n1[10];
#pragma unroll
    for (int k = 0; k < 10; k++) n1[k] = nv1[v * 10 + k];
    float a[4];
#pragma unroll
    for (int j = 0; j < 4; j++) {
        int w = tid + j * 256;
        float s = 0.f;
#pragma unroll
        for (int k = 0; k < 10; k++) s += n1[k] * nv2[k * 1024 + w];
        a[j] = fmaxf(s, 0.f);
    }
    float mx = fmaxf(fmaxf(a[0], a[1]), fmaxf(a[2], a[3]));
    red[tid] = mx; __syncthreads();
    for (int s = 128; s > 0; s >>= 1) {
        if (tid < s) red[tid] = fmaxf(red[tid], red[tid + s]);
        __syncthreads();
    }
    mx = red[0]; __syncthreads();
    float e[4]; float sum = 0.f;
#pragma unroll
    for (int j = 0; j < 4; j++) { e[j] = expf(a[j] - mx); sum += e[j]; }
    red[tid] = sum; __syncthreads();
    for (int s = 128; s > 0; s >>= 1) {
        if (tid < s) red[tid] += red[tid + s];
        __syncthreads();
    }
    float inv = 1.f / red[0];
#pragma unroll
    for (int j = 0; j < 4; j++) {
        int w = tid + j * 256;
        float val = e[j] * inv;
        adpf[(long)v * 1024 + w] = val;
        Bpk[((long)(v >> 1) * 1024 + w) * 2 + (v & 1)] = __float2half(val);
    }
}

// ---------------------------------------------------------------------------
__global__ __launch_bounds__(256) void k_start(const float* __restrict__ x,
                                               const float* __restrict__ sw,
                                               const float* __restrict__ sb,
                                               float* __restrict__ h) {
    int bl = blockIdx.x;
    int b = bl / 13, l = bl - b * 13;
    int n = blockIdx.y * 256 + threadIdx.x;
    float x0 = x[(((long)b * 2 + 0) * 1024 + n) * 13 + l];
    float x1 = x[(((long)b * 2 + 1) * 1024 + n) * 13 + l];
    float* hb = h + ((long)(b * 13 + l) * 32) * 1024 + n;
#pragma unroll
    for (int c = 0; c < 32; c++)
        hb[(long)c * 1024] = sw[c * 2] * x0 + sw[c * 2 + 1] * x1 + sb[c];
}

// ---------------------------------------------------------------------------
// dilated conv + gated activation + gc channel premix, packed fp32x2 FMA.
// ---------------------------------------------------------------------------
__global__ __launch_bounds__(256) void k_dconv(const float* __restrict__ h,
                                               const float* __restrict__ fw,
                                               const float* __restrict__ fb,
                                               const float* __restrict__ gw,
                                               const float* __restrict__ gb,
                                               const float* __restrict__ gcw,
                                               const float* __restrict__ gcb,
                                               __half* __restrict__ mmA,
                                               __half* __restrict__ mm0,
                                               __half* __restrict__ msk,
                                               int L0, int L1, int d, int layer,
                                               int doPre) {
    __shared__ float  s_in[2][32][64];
    __shared__ float4 s_wf[32][16];
    __shared__ float4 s_wg[32][16];
    __shared__ float4 s_wpA[32][16];
    __shared__ float2 s_wpB[32][16];
    __shared__ unsigned long long s_fbp[16], s_gbp[16], s_gcbp[16];

    int bl = blockIdx.x;
    int b = bl / L1, l = bl - b * L1;
    int n0 = blockIdx.y * 64;
    int tid = threadIdx.x;

    for (int idx = tid; idx < 512; idx += 256) {
        int ci = idx >> 4, p = idx & 15;
        int co0 = p * 2, co1 = p * 2 + 1;
        int o0 = (co0 * 32 + ci) * 2, o1 = (co1 * 32 + ci) * 2;
        s_wf[ci][p] = make_float4(fw[o0], fw[o1], fw[o0 + 1], fw[o1 + 1]);
        s_wg[ci][p] = make_float4(gw[o0], gw[o1], gw[o0 + 1], gw[o1 + 1]);
        if (doPre) {
            s_wpA[ci][p] = make_float4(gcw[co0 * 96 + ci], gcw[co1 * 96 + ci],
                                       gcw[co0 * 96 + 32 + ci], gcw[co1 * 96 + 32 + ci]);
            s_wpB[ci][p] = make_float2(gcw[co0 * 96 + 64 + ci], gcw[co1 * 96 + 64 + ci]);
        }
    }
    if (tid < 16) {
        s_fbp[tid] = packf2(fb[2 * tid], fb[2 * tid + 1]);
        s_gbp[tid] = packf2(gb[2 * tid], gb[2 * tid + 1]);
        s_gcbp[tid] = doPre ? packf2(gcb[2 * tid], gcb[2 * tid + 1]) : 0ull;
    }
    const float* hb = h + ((long)(b * L0 + l) * 32) * 1024 + n0;
    for (int idx = tid; idx < 4096; idx += 256) {
        int tap = idx >> 11, ci = (idx >> 6) & 31, nl = idx & 63;
        s_in[tap][ci][nl] = hb[((long)(tap * d) * 32 + ci) * 1024 + nl];
    }
    __syncthreads();

    int nl = tid & 63, cg = tid >> 6;
    unsigned long long fa2[4], ga2[4];
#pragma unroll
    for (int p = 0; p < 4; p++) { fa2[p] = s_fbp[cg * 4 + p]; ga2[p] = s_gbp[cg * 4 + p]; }
#pragma unroll
    for (int ci = 0; ci < 32; ci++) {
        float v0 = s_in[0][ci][nl], v1 = s_in[1][ci][nl];
        unsigned long long vv0 = packf2(v0, v0), vv1 = packf2(v1, v1);
#pragma unroll
        for (int p = 0; p < 4; p++) {
            ulonglong2 wf = *(const ulonglong2*)&s_wf[ci][cg * 4 + p];
            FMA2(fa2[p], wf.x, vv0);
            FMA2(fa2[p], wf.y, vv1);
            ulonglong2 wg = *(const ulonglong2*)&s_wg[ci][cg * 4 + p];
            FMA2(ga2[p], wg.x, vv0);
            FMA2(ga2[p], wg.y, vv1);
        }
    }

    bool last = (l == L1 - 1);
    long col = (long)b * 1024 + n0 + nl;
    float mval[8];
#pragma unroll
    for (int p = 0; p < 4; p++) {
        float flo, fhi, glo, ghi;
        unpackf2(fa2[p], flo, fhi);
        unpackf2(ga2[p], glo, ghi);
        mval[2 * p]     = gated_act(flo, glo);
        mval[2 * p + 1] = gated_act(fhi, ghi);
    }
#pragma unroll
    for (int u = 0; u < 8; u++) {
        if (last) {
            int k = layer * 32 + cg * 8 + u;
            msk[((long)(k >> 1) * 65536 + col) * 2 + (k & 1)] = __float2half(mval[u]);
        }
    }
    if (!doPre) return;

    __syncthreads();
    float (*s_m)[64] = s_in[0];
#pragma unroll
    for (int u = 0; u < 8; u++) s_m[cg * 8 + u][nl] = mval[u];
    __syncthreads();

    unsigned long long p02[4], p12[4], p22[4];
#pragma unroll
    for (int p = 0; p < 4; p++) { p02[p] = s_gcbp[cg * 4 + p]; p12[p] = 0ull; p22[p] = 0ull; }
#pragma unroll
    for (int ci = 0; ci < 32; ci++) {
        float v = s_m[ci][nl];
        unsigned long long vv = packf2(v, v);
#pragma unroll
        for (int p = 0; p < 4; p++) {
            ulonglong2 wa = *(const ulonglong2*)&s_wpA[ci][cg * 4 + p];
            FMA2(p02[p], wa.x, vv);
            FMA2(p12[p], wa.y, vv);
            unsigned long long wb = *(const unsigned long long*)&s_wpB[ci][cg * 4 + p];
            FMA2(p22[p], wb, vv);
        }
    }
    long rowbase = (long)(b * L1 + l) * 32;
#pragma unroll
    for (int p = 0; p < 4; p++) {
        float a0, a1, b0, b1, c0, c1;
        unpackf2(p02[p], a0, a1);
        unpackf2(p12[p], b0, b1);
        unpackf2(p22[p], c0, c1);
        long r0 = rowbase + cg * 8 + 2 * p;
        long r1 = r0 + 1;
        mm0[r0 * 1024 + n0 + nl] = __float2half(a0);
        mm0[r1 * 1024 + n0 + nl] = __float2half(a1);
        mmA[r0 * 2048 + n0 + nl] = __float2half(b0);
        mmA[r1 * 2048 + n0 + nl] = __float2half(b1);
        mmA[r0 * 2048 + 1024 + n0 + nl] = __float2half(c0);
        mmA[r1 * 2048 + 1024 + n0 + nl] = __float2half(c1);
    }
}

// ---------------------------------------------------------------------------
// fp32 SIMT SGEMM: ADP^2 = ADP @ ADP; k-packed half into Bpk rows 512..1023
// ---------------------------------------------------------------------------
__global__ __launch_bounds__(256) void k_sgemm(const float* __restrict__ A,
                                               const float* __restrict__ B,
                                               __half* __restrict__ Bpk) {
    __shared__ float As[16][132];
    __shared__ float Bs[16][128];
    int tid = threadIdx.x;
    int m0 = blockIdx.y * 128, n0 = blockIdx.x * 128;
    int ty = tid >> 4, tx = tid & 15;
    float acc[8][8];
#pragma unroll
    for (int i = 0; i < 8; i++)
#pragma unroll
        for (int j = 0; j < 8; j++) acc[i][j] = 0.f;

    for (int k0 = 0; k0 < 1024; k0 += 16) {
#pragma unroll
        for (int i = 0; i < 2; i++) {
            int f = tid + i * 256;
            int r = f >> 2, kc = (f & 3) * 4;
            float4 v = *(const float4*)(A + (long)(m0 + r) * 1024 + k0 + kc);
            As[kc + 0][r] = v.x; As[kc + 1][r] = v.y;
            As[kc + 2][r] = v.z; As[kc + 3][r] = v.w;
        }
#pragma unroll
        for (int i = 0; i < 2; i++) {
            int f = tid + i * 256;
            int r = f >> 5, nc = (f & 31) * 4;
            float4 v = *(const float4*)(B + (long)(k0 + r) * 1024 + n0 + nc);
            *(float4*)&Bs[r][nc] = v;
        }
        __syncthreads();
#pragma unroll
        for (int k = 0; k < 16; k++) {
            float a[8], b[8];
            float4 a0 = *(const float4*)&As[k][ty * 8];
            float4 a1 = *(const float4*)&As[k][ty * 8 + 4];
            a[0] = a0.x; a[1] = a0.y; a[2] = a0.z; a[3] = a0.w;
            a[4] = a1.x; a[5] = a1.y; a[6] = a1.z; a[7] = a1.w;
            float4 b0 = *(const float4*)&Bs[k][tx * 8];
            float4 b1 = *(const float4*)&Bs[k][tx * 8 + 4];
            b[0] = b0.x; b[1] = b0.y; b[2] = b0.z; b[3] = b0.w;
            b[4] = b1.x; b[5] = b1.y; b[6] = b1.z; b[7] = b1.w;
#pragma unroll
            for (int i = 0; i < 8; i++)
#pragma unroll
                for (int j = 0; j < 8; j++) acc[i][j] += a[i] * b[j];
        }
        __syncthreads();
    }
#pragma unroll
    for (int i = 0; i < 8; i++) {
        int v = m0 + ty * 8 + i;
#pragma unroll
        for (int j = 0; j < 8; j++) {
            int w = n0 + tx * 8 + j;
            Bpk[((long)(512 + (v >> 1)) * 1024 + w) * 2 + (v & 1)] =
                __float2half(acc[i][j]);
        }
    }
}

// ---------------------------------------------------------------------------
// gc-tail epilogue helper (shared by both GEMM variants)
// ---------------------------------------------------------------------------
__device__ __forceinline__ void gc_epilogue_rowpair(
    float* hnew, const float* hold, const __half* mm0,
    const float* bng, const float* bnb,
    int L0, int L1, int d, int row0, int wn_base, int n0, int tg,
    const float (*accRow)[4], int ntcount) {
    const float rs = rsqrtf(1.f + 1e-5f);
    int row1 = row0 + 8;
    int blx = row0 >> 5;
    int b = blx / L1, l = blx - b * L1;
    long hbase = (long)(b * L0 + l + d) * 32;
    int co0 = row0 & 31, co1 = row1 & 31;
    float sc0 = bng[co0] * rs, sh0 = bnb[co0];
    float sc1 = bng[co1] * rs, sh1 = bnb[co1];
    for (int nt = 0; nt < ntcount; nt++) {
        int col = n0 + wn_base + nt * 8 + tg * 2;
        half2 q0 = *(const half2*)&mm0[(long)row0 * 1024 + col];
        half2 q1 = *(const half2*)&mm0[(long)row1 * 1024 + col];
        float2 r0 = *(const float2*)&hold[(hbase + co0) * 1024 + col];
        float2 r1 = *(const float2*)&hold[(hbase + co1) * 1024 + col];
        float2 o0, o1;
        o0.x = (accRow[nt][0] + __half2float(q0.x) + r0.x) * sc0 + sh0;
        o0.y = (accRow[nt][1] + __half2float(q0.y) + r0.y) * sc0 + sh0;
        o1.x = (accRow[nt][2] + __half2float(q1.x) + r1.x) * sc1 + sh1;
        o1.y = (accRow[nt][3] + __half2float(q1.y) + r1.y) * sc1 + sh1;
        *(float2*)&hnew[(long)row0 * 1024 + col] = o0;
        *(float2*)&hnew[(long)row1 * 1024 + col] = o1;
    }
}

// ---------------------------------------------------------------------------
// fused layer GEMM + gc tail, BN=256 (large-M layers).
// ---------------------------------------------------------------------------
__global__ __launch_bounds__(256) void k_gemm_gc(const __half* __restrict__ A,
                                                 const half2* __restrict__ Bpk,
                                                 float* __restrict__ hnew,
                                                 const float* __restrict__ hold,
                                                 const __half* __restrict__ mm0,
                                                 const float* __restrict__ bng,
                                                 const float* __restrict__ bnb,
                                                 int L0, int L1, int d) {
    __shared__ __half As[2][128][40];
    __shared__ half2  Bs[2][16][264];
    int tid = threadIdx.x;
    int m0 = blockIdx.y * 128;
    int n0 = blockIdx.x * 256;
    int w = tid >> 5, lane = tid & 31;
    int grp = lane >> 2, tg = lane & 3;
    int wm = (w & 1) * 64, wn = (w >> 1) * 64;
    int arow = lane & 15, akoff = (lane >> 4) * 8;
    unsigned asBase = (unsigned)__cvta_generic_to_shared(&As[0][0][0]);

    float acc[4][8][4];
#pragma unroll
    for (int mt = 0; mt < 4; mt++)
#pragma unroll
        for (int nt = 0; nt < 8; nt++)
#pragma unroll
            for (int c = 0; c < 4; c++) acc[mt][nt][c] = 0.f;

    const int nstage = 2048 / 32;
    {
#pragma unroll
        for (int i = 0; i < 2; i++) {
            int ch = tid + i * 256;
            int r = ch >> 2, p = (ch & 3) * 8;
            cp16(&As[0][r][p], A + (long)(m0 + r) * 2048 + p);
        }
#pragma unroll
        for (int i = 0; i < 4; i++) {
            int ch = tid + i * 256;
            int r = ch >> 6, c4 = (ch & 63) * 4;
            cp16(&Bs[0][r][c4], Bpk + (long)r * 1024 + n0 + c4);
        }
        asm volatile("cp.async.commit_group;\n");
    }

    for (int s = 0; s < nstage; s++) {
        int buf = s & 1;
        if (s + 1 < nstage) {
            int nb = buf ^ 1;
            int k0 = (s + 1) * 32;
#pragma unroll
            for (int i = 0; i < 2; i++) {
                int ch = tid + i * 256;
                int r = ch >> 2, p = (ch & 3) * 8;
                cp16(&As[nb][r][p], A + (long)(m0 + r) * 2048 + k0 + p);
            }
#pragma unroll
            for (int i = 0; i < 4; i++) {
                int ch = tid + i * 256;
                int r = ch >> 6, c4 = (ch & 63) * 4;
                cp16(&Bs[nb][r][c4], Bpk + (long)(k0 / 2 + r) * 1024 + n0 + c4);
            }
            asm volatile("cp.async.commit_group;\n");
            asm volatile("cp.async.wait_group 1;\n");
        } else {
            asm volatile("cp.async.wait_group 0;\n");
        }
        __syncthreads();

#pragma unroll
        for (int s2 = 0; s2 < 2; s2++) {
            unsigned a[4][4];
#pragma unroll
            for (int mt = 0; mt < 4; mt++) {
                unsigned addr = asBase +
                    (unsigned)(((buf << 7) + wm + mt * 16 + arow) * 40 +
                               s2 * 16 + akoff) * 2;
                asm volatile(
                    "ldmatrix.sync.aligned.m8n8.x4.shared.b16 {%0,%1,%2,%3}, [%4];\n"
                    : "=r"(a[mt][0]), "=r"(a[mt][1]), "=r"(a[mt][2]), "=r"(a[mt][3])
                    : "r"(addr));
            }
            unsigned b[8][2];
#pragma unroll
            for (int nt = 0; nt < 8; nt++) {
                int cb = wn + nt * 8 + grp;
                b[nt][0] = *(const unsigned*)&Bs[buf][s2 * 8 + tg][cb];
                b[nt][1] = *(const unsigned*)&Bs[buf][s2 * 8 + tg + 4][cb];
            }
#pragma unroll
            for (int mt = 0; mt < 4; mt++)
#pragma unroll
                for (int nt = 0; nt < 8; nt++) {
                    asm volatile(
                        "mma.sync.aligned.m16n8k16.row.col.f32.f16.f16.f32 "
                        "{%0,%1,%2,%3}, {%4,%5,%6,%7}, {%8,%9}, {%0,%1,%2,%3};\n"
                        : "+f"(acc[mt][nt][0]), "+f"(acc[mt][nt][1]),
                          "+f"(acc[mt][nt][2]), "+f"(acc[mt][nt][3])
                        : "r"(a[mt][0]), "r"(a[mt][1]), "r"(a[mt][2]), "r"(a[mt][3]),
                          "r"(b[nt][0]), "r"(b[nt][1]));
                }
        }
        __syncthreads();
    }

#pragma unroll
    for (int mt = 0; mt < 4; mt++)
        gc_epilogue_rowpair(hnew, hold, mm0, bng, bnb, L0, L1, d,
                            m0 + wm + mt * 16 + grp, wn, n0, tg, acc[mt], 8);
}

// ---------------------------------------------------------------------------
// fused layer GEMM + gc tail, BN=128 (small-M layers: 2x more CTAs).
// 8 warps as 4(m) x 2(n); warp tile 32x64.
// ---------------------------------------------------------------------------
__global__ __launch_bounds__(256) void k_gemm_gc128(const __half* __restrict__ A,
                                                    const half2* __restrict__ Bpk,
                                                    float* __restrict__ hnew,
                                                    const float* __restrict__ hold,
                                                    const __half* __restrict__ mm0,
                                                    const float* __restrict__ bng,
                                                    const float* __restrict__ bnb,
                                                    int L0, int L1, int d) {
    __shared__ __half As[2][128][40];
    __shared__ half2  Bs[2][16][136];
    int tid = threadIdx.x;
    int m0 = blockIdx.y * 128;
    int n0 = blockIdx.x * 128;
    int w = tid >> 5, lane = tid & 31;
    int grp = lane >> 2, tg = lane & 3;
    int wm = (w & 3) * 32, wn = (w >> 2) * 64;
    int arow = lane & 15, akoff = (lane >> 4) * 8;
    unsigned asBase = (unsigned)__cvta_generic_to_shared(&As[0][0][0]);

    float acc[2][8][4];
#pragma unroll
    for (int mt = 0; mt < 2; mt++)
#pragma unroll
        for (int nt = 0; nt < 8; nt++)
#pragma unroll
            for (int c = 0; c < 4; c++) acc[mt][nt][c] = 0.f;

    const int nstage = 2048 / 32;
    {
#pragma unroll
        for (int i = 0; i < 2; i++) {
            int ch = tid + i * 256;
            int r = ch >> 2, p = (ch & 3) * 8;
            cp16(&As[0][r][p], A + (long)(m0 + r) * 2048 + p);
        }
#pragma unroll
        for (int i = 0; i < 2; i++) {
            int ch = tid + i * 256;
            int r = ch >> 5, c4 = (ch & 31) * 4;
            cp16(&Bs[0][r][c4], Bpk + (long)r * 1024 + n0 + c4);
        }
        asm volatile("cp.async.commit_group;\n");
    }

    for (int s = 0; s < nstage; s++) {
        int buf = s & 1;
        if (s + 1 < nstage) {
            int nb = buf ^ 1;
            int k0 = (s + 1) * 32;
#pragma unroll
            for (int i = 0; i < 2; i++) {
                int ch = tid + i * 256;
                int r = ch >> 2, p = (ch & 3) * 8;
                cp16(&As[nb][r][p], A + (long)(m0 + r) * 2048 + k0 + p);
            }
#pragma unroll
            for (int i = 0; i < 2; i++) {
                int ch = tid + i * 256;
                int r = ch >> 5, c4 = (ch & 31) * 4;
                cp16(&Bs[nb][r][c4], Bpk + (long)(k0 / 2 + r) * 1024 + n0 + c4);
            }
            asm volatile("cp.async.commit_group;\n");
            asm volatile("cp.async.wait_group 1;\n");
        } else {
            asm volatile("cp.async.wait_group 0;\n");
        }
        __syncthreads();

#pragma unroll
        for (int s2 = 0; s2 < 2; s2++) {
            unsigned a[2][4];
#pragma unroll
            for (int mt = 0; mt < 2; mt++) {
                unsigned addr = asBase +
                    (unsigned)(((buf << 7) + wm + mt * 16 + arow) * 40 +
                               s2 * 16 + akoff) * 2;
                asm volatile(
                    "ldmatrix.sync.aligned.m8n8.x4.shared.b16 {%0,%1,%2,%3}, [%4];\n"
                    : "=r"(a[mt][0]), "=r"(a[mt][1]), "=r"(a[mt][2]), "=r"(a[mt][3])
                    : "r"(addr));
            }
            unsigned b[8][2];
#pragma unroll
            for (int nt = 0; nt < 8; nt++) {
                int cb = wn + nt * 8 + grp;
                b[nt][0] = *(const unsigned*)&Bs[buf][s2 * 8 + tg][cb];
                b[nt][1] = *(const unsigned*)&Bs[buf][s2 * 8 + tg + 4][cb];
            }
#pragma unroll
            for (int mt = 0; mt < 2; mt++)
#pragma unroll
                for (int nt = 0; nt < 8; nt++) {
                    asm volatile(
                        "mma.sync.aligned.m16n8k16.row.col.f32.f16.f16.f32 "
                        "{%0,%1,%2,%3}, {%4,%5,%6,%7}, {%8,%9}, {%0,%1,%2,%3};\n"
                        : "+f"(acc[mt][nt][0]), "+f"(acc[mt][nt][1]),
                          "+f"(acc[mt][nt][2]), "+f"(acc[mt][nt][3])
                        : "r"(a[mt][0]), "r"(a[mt][1]), "r"(a[mt][2]), "r"(a[mt][3]),
                          "r"(b[nt][0]), "r"(b[nt][1]));
                }
        }
        __syncthreads();
    }

#pragma unroll
    for (int mt = 0; mt < 2; mt++)
        gc_epilogue_rowpair(hnew, hold, mm0, bng, bnb, L0, L1, d,
                            m0 + wm + mt * 16 + grp, wn, n0, tg, acc[mt], 8);
}

// ---------------------------------------------------------------------------
// generic fp16 GEMM, ldmatrix A, 2-stage. flags:
// bit1: +bias relu. bit2: C k-packed half. bit3: C plain half.
// bit4: end2 mode. else: C fp32.
// ---------------------------------------------------------------------------
__global__ __launch_bounds__(256) void k_gemm_f16(const __half* __restrict__ A,
                                                  const half2* __restrict__ Bpk,
                                                  void* __restrict__ Cv,
                                                  int K, int lda, long ldb2, long ldc,
                                                  const float* __restrict__ bias,
                                                  int flags) {
    __shared__ __half As[2][128][40];
    __shared__ half2  Bs[2][16][264];
    int tid = threadIdx.x;
    int m0 = blockIdx.y * 128;
    long n0 = (long)blockIdx.x * 256;
    int w = tid >> 5, lane = tid & 31;
    int grp = lane >> 2, tg = lane & 3;
    int wm = (w & 1) * 64, wn = (w >> 1) * 64;
    int arow = lane & 15, akoff = (lane >> 4) * 8;
    unsigned asBase = (unsigned)__cvta_generic_to_shared(&As[0][0][0]);

    float acc[4][8][4];
#pragma unroll
    for (int mt = 0; mt < 4; mt++)
#pragma unroll
        for (int nt = 0; nt < 8; nt++)
#pragma unroll
            for (int c = 0; c < 4; c++) acc[mt][nt][c] = 0.f;

    int nstage = K / 32;
    {
#pragma unroll
        for (int i = 0; i < 2; i++) {
            int ch = tid + i * 256;
            int r = ch >> 2, p = (ch & 3) * 8;
            cp16(&As[0][r][p], A + (long)(m0 + r) * lda + p);
        }
#pragma unroll
        for (int i = 0; i < 4; i++) {
            int ch = tid + i * 256;
            int r = ch >> 6, c4 = (ch & 63) * 4;
            cp16(&Bs[0][r][c4], Bpk + (long)r * ldb2 + n0 + c4);
        }
        asm volatile("cp.async.commit_group;\n");
    }

    for (int s = 0; s < nstage; s++) {
        int buf = s & 1;
        if (s + 1 < nstage) {
            int nb = buf ^ 1;
            int k0 = (s + 1) * 32;
#pragma unroll
            for (int i = 0; i < 2; i++) {
                int ch = tid + i * 256;
                int r = ch >> 2, p = (ch & 3) * 8;
                cp16(&As[nb][r][p], A + (long)(m0 + r) * lda + k0 + p);
            }
#pragma unroll
            for (int i = 0; i < 4; i++) {
                int ch = tid + i * 256;
                int r = ch >> 6, c4 = (ch & 63) * 4;
                cp16(&Bs[nb][r][c4], Bpk + (long)(k0 / 2 + r) * ldb2 + n0 + c4);
            }
            asm volatile("cp.async.commit_group;\n");
            asm volatile("cp.async.wait_group 1;\n");
        } else {
            asm volatile("cp.async.wait_group 0;\n");
        }
        __syncthreads();

#pragma unroll
        for (int s2 = 0; s2 < 2; s2++) {
            unsigned a[4][4];
#pragma unroll
            for (int mt = 0; mt < 4; mt++) {
                unsigned addr = asBase +
                    (unsigned)(((buf << 7) + wm + mt * 16 + arow) * 40 +
                               s2 * 16 + akoff) * 2;
                asm volatile(
                    "ldmatrix.sync.aligned.m8n8.x4.shared.b16 {%0,%1,%2,%3}, [%4];\n"
                    : "=r"(a[mt][0]), "=r"(a[mt][1]), "=r"(a[mt][2]), "=r"(a[mt][3])
                    : "r"(addr));
            }
            unsigned b[8][2];
#pragma unroll
            for (int nt = 0; nt < 8; nt++) {
                int cb = wn + nt * 8 + grp;
                b[nt][0] = *(const unsigned*)&Bs[buf][s2 * 8 + tg][cb];
                b[nt][1] = *(const unsigned*)&Bs[buf][s2 * 8 + tg + 4][cb];
            }
#pragma unroll
            for (int mt = 0; mt < 4; mt++)
#pragma unroll
                for (int nt = 0; nt < 8; nt++) {
                    asm volatile(
                        "mma.sync.aligned.m16n8k16.row.col.f32.f16.f16.f32 "
                        "{%0,%1,%2,%3}, {%4,%5,%6,%7}, {%8,%9}, {%0,%1,%2,%3};\n"
                        : "+f"(acc[mt][nt][0]), "+f"(acc[mt][nt][1]),
                          "+f"(acc[mt][nt][2]), "+f"(acc[mt][nt][3])
                        : "r"(a[mt][0]), "r"(a[mt][1]), "r"(a[mt][2]), "r"(a[mt][3]),
                          "r"(b[nt][0]), "r"(b[nt][1]));
                }
        }
        __syncthreads();
    }

    float* Cf = (float*)Cv;
    __half* Ch = (__half*)Cv;
#pragma unroll
    for (int mt = 0; mt < 4; mt++) {
        int row0 = m0 + wm + mt * 16 + grp;
        int row1 = row0 + 8;
        float b0 = 0.f, b1 = 0.f;
        if (flags & (2 | 16)) { b0 = bias[row0]; b1 = bias[row1]; }
#pragma unroll
        for (int nt = 0; nt < 8; nt++) {
            long col = n0 + wn + nt * 8 + tg * 2;
            float v00 = acc[mt][nt][0], v01 = acc[mt][nt][1];
            float v10 = acc[mt][nt][2], v11 = acc[mt][nt][3];
            if (flags & 2) {
                v00 = fmaxf(v00 + b0, 0.f); v01 = fmaxf(v01 + b0, 0.f);
                v10 = fmaxf(v10 + b1, 0.f); v11 = fmaxf(v11 + b1, 0.f);
            } else if (flags & 16) {
                v00 += b0; v01 += b0; v10 += b1; v11 += b1;
            }
            if (flags & 16) {
                long bidx = col >> 10;
                long n = col & 1023;
                if (row0 < 12)
                    *(float2*)(Cf + (bidx * 12 + row0) * 1024 + n) =
                        make_float2(v00, v01);
                if (row1 < 12)
                    *(float2*)(Cf + (bidx * 12 + row1) * 1024 + n) =
                        make_float2(v10, v11);
            } else if (flags & 4) {
                long p0 = ((long)(row0 >> 1) * ldc + col) * 2 + (row0 & 1);
                long p1 = ((long)(row1 >> 1) * ldc + col) * 2 + (row1 & 1);
                Ch[p0] = __float2half(v00); Ch[p0 + 2] = __float2half(v01);
                Ch[p1] = __float2half(v10); Ch[p1 + 2] = __float2half(v11);
            } else if (flags & 8) {
                *(half2*)(Ch + (long)row0 * ldc + col) = __floats2half2_rn(v00, v01);
                *(half2*)(Ch + (long)row1 * ldc + col) = __floats2half2_rn(v10, v11);
            } else {
                *(float2*)(Cf + (long)row0 * ldc + col) = make_float2(v00, v01);
                *(float2*)(Cf + (long)row1 * ldc + col) = make_float2(v10, v11);
            }
        }
    }
}

// ---------------------------------------------------------------------------
__global__ __launch_bounds__(256) void k_prep_all(const float* __restrict__ end1_w,
                                                  const float* __restrict__ skw,
                                                  const float* __restrict__ skb,
                                                  const float* __restrict__ w2,
                                                  const float* __restrict__ b2,
                                                  __half* __restrict__ w1r,
                                                  __half* __restrict__ wcat,
                                                  float* __restrict__ bsum,
                                                  __half* __restrict__ w2p,
                                                  float* __restrict__ b2p) {
    int blk = blockIdx.x;
    int tid = threadIdx.x;
    if (blk < 512) {
        int i = blk * 256 + tid;
        w1r[i] = __float2half(end1_w[i]);
    } else if (blk < 768) {
        int co = blk - 512, k = tid;
        int i = k >> 5, ci = k & 31;
        wcat[co * 256 + k] = __float2half(skw[((long)i * 256 + co) * 32 + ci]);
        if (k == 0) {
            float s = 0.f;
#pragma unroll
            for (int j = 0; j < 8; j++) s += skb[j * 256 + co];
            bsum[co] = s;
        }
    } else {
        int o = blk - 768;
#pragma unroll
        for (int i = 0; i < 2; i++) {
            int k = tid + i * 256;
            w2p[o * 512 + k] = (o < 12) ? __float2half(w2[o * 512 + k])
                                        : __float2half(0.f);
        }
        if (tid == 0) b2p[o] = (o < 12) ? b2[o] : 0.f;
    }
}

// ---------------------------------------------------------------------------
extern "C" void kernel_launch(void* const* d_in, const int* in_sizes, int n_in,
                              void* d_out, int out_size) {
    const float* x        = (const float*)d_in[0];
    const float* start_w  = (const float*)d_in[1];
    const float* start_b  = (const float*)d_in[2];
    const float* nodevec1 = (const float*)d_in[3];
    const float* nodevec2 = (const float*)d_in[4];
    const float* filter_w = (const float*)d_in[5];
    const float* filter_b = (const float*)d_in[6];
    const float* gate_w   = (const float*)d_in[7];
    const float* gate_b   = (const float*)d_in[8];
    const float* skip_w   = (const float*)d_in[9];
    const float* skip_b   = (const float*)d_in[10];
    const float* gc_w     = (const float*)d_in[11];
    const float* gc_b     = (const float*)d_in[12];
    const float* bn_g     = (const float*)d_in[13];
    const float* bn_b     = (const float*)d_in[14];
    const float* end1_w   = (const float*)d_in[15];
    const float* end1_b   = (const float*)d_in[16];
    const float* end2_w   = (const float*)d_in[17];
    const float* end2_b   = (const float*)d_in[18];

    float *hA, *hB, *adpf, *bsk, *b2p;
    __half *mmA, *mm0, *Bm, *msk, *skip, *e1, *w1r, *wsk, *w2p;
    cudaGetSymbolAddress((void**)&hA, g_hA);
    cudaGetSymbolAddress((void**)&hB, g_hB);
    cudaGetSymbolAddress((void**)&mmA, g_mmA);
    cudaGetSymbolAddress((void**)&mm0, g_mm0);
    cudaGetSymbolAddress((void**)&adpf, g_adpf);
    cudaGetSymbolAddress((void**)&Bm, g_Bm);
    cudaGetSymbolAddress((void**)&msk, g_msk);
    cudaGetSymbolAddress((void**)&skip, g_skip);
    cudaGetSymbolAddress((void**)&e1, g_e1);
    cudaGetSymbolAddress((void**)&w1r, g_w1r);
    cudaGetSymbolAddress((void**)&wsk, g_wsk);
    cudaGetSymbolAddress((void**)&bsk, g_bsk);
    cudaGetSymbolAddress((void**)&w2p, g_w2p);
    cudaGetSymbolAddress((void**)&b2p, g_b2p);

    k_adp<<<1024, 256>>>(nodevec1, nodevec2, adpf, Bm);
    k_sgemm<<<dim3(8, 8), 256>>>(adpf, adpf, Bm);
    k_start<<<dim3(64 * 13, 4), 256>>>(x, start_w, start_b, hA);
    k_prep_all<<<896, 256>>>(end1_w, skip_w, skip_b, end2_w, end2_b,
                             w1r, wsk, bsk, w2p, b2p);

    const int lens[9] = {13, 12, 10, 9, 7, 6, 4, 3, 1};
    const int dil[8]  = {1, 2, 1, 2, 1, 2, 1, 2};
    float* hcur = hA;
    float* hnext = hB;

    for (int i = 0; i < 8; i++) {
        int L0 = lens[i], L1 = lens[i + 1], d = dil[i];
        int doPre = (i < 7) ? 1 : 0;
        k_dconv<<<dim3(64 * L1, 16), 256>>>(hcur,
                                            filter_w + i * 2048, filter_b + i * 32,
                                            gate_w + i * 2048, gate_b + i * 32,
                                            gc_w + i * 32 * 96, gc_b + i * 32,
                                            mmA, mm0, msk, L0, L1, d, i, doPre);
        if (i < 7) {
            int M = 2048 * L1;
            if (L1 <= 7) {
                // small-M layers: BN=128, 2x more CTAs for occupancy
                k_gemm_gc128<<<dim3(8, M / 128), 256>>>(
                    mmA, (const half2*)Bm, hnext, hcur, mm0,
                    bn_g + i * 32, bn_b + i * 32, L0, L1, d);
            } else {
                k_gemm_gc<<<dim3(4, M / 128), 256>>>(
                    mmA, (const half2*)Bm, hnext, hcur, mm0,
                    bn_g + i * 32, bn_b + i * 32, L0, L1, d);
            }
            float* t = hcur; hcur = hnext; hnext = t;
        }
    }

    // skip = relu(Wcat @ msk + bsum), k-packed half
    k_gemm_f16<<<dim3(65536 / 256, 2), 256>>>(
        wsk, (const half2*)msk, skip, 256, 256, 65536, 65536, bsk, 2 | 4);
    // e1 = relu(W1 @ skip + b1), k-packed half (B operand for end2 GEMM)
    k_gemm_f16<<<dim3(65536 / 256, 4), 256>>>(
        w1r, (const half2*)skip, e1, 256, 256, 65536, 65536, end1_b, 2 | 4);
    // out = W2 @ e1 + b2  (padded M=128, rows<12 stored with [b][o][n] mapping)
    k_gemm_f16<<<dim3(65536 / 256, 1), 256>>>(
        w2p, (const half2*)e1, (float*)d_out, 512, 512, 65536, 0, b2p, 16);
}

// round 17
// speedup vs baseline: 1.5226x; 1.1322x over previous
#include <cuda_runtime.h>
#include <cuda_fp16.h>
#include <math.h>
#include <stdint.h>

// ---------------------------------------------------------------------------
// GWNet2: B=64, N=1024, L=13, RC=DC=32, SC=256, EC=512, OUT=12, LAYERS=8
// h layout: [B][L][C][N] fp32.
// dconv: conv + gated act only; stores m k-packed. gc premix moved to a
// K=32 tensor-core GEMM (k_gemm_pre) producing mmA/mm0.
// GEMMs: mma.sync m16n8k16 f16/f32acc, cp.async, ldmatrix A frags.
// ---------------------------------------------------------------------------

__device__ float  g_hA  [64 * 13 * 32 * 1024];
__device__ float  g_hB  [64 * 12 * 32 * 1024];
__device__ __half g_mmA [64 * 12 * 32 * 2048];       // [mm1 | mm2], A operand
__device__ __half g_mm0 [64 * 12 * 32 * 1024];       // Wm@m + gcb
__device__ __half g_mpk [16 * 786432 * 2];           // m k-packed: [16 k2][B*L1*1024]
__device__ float  g_adpf[1024 * 1024];               // ADP fp32 (for ADP^2)
__device__ __half g_Bm  [2048 * 1024];               // k-packed [ADP ; ADP^2]
__device__ __half g_msk [256 * 65536];               // k-packed concat m_last
__device__ __half g_skip[256 * 65536];               // k-packed relu(skip)
__device__ __half g_e1  [512 * 65536];               // k-packed relu(e1)
__device__ __half g_w1r [512 * 256];
__device__ __half g_wsk [256 * 256];
__device__ float  g_bsk [256];
__device__ __half g_w2p [128 * 512];                 // padded end2 weights
__device__ float  g_b2p [128];
__device__ __half g_wgc [7 * 128 * 32];              // premix weights, padded M=128

// ---------------------------------------------------------------------------
__device__ __forceinline__ void cp16(void* smem, const void* g) {
    unsigned s = (unsigned)__cvta_generic_to_shared(smem);
    asm volatile("cp.async.cg.shared.global [%0], [%1], 16;\n" :: "r"(s), "l"(g));
}
__device__ __forceinline__ unsigned long long packf2(float lo, float hi) {
    unsigned long long r;
    asm("mov.b64 %0, {%1, %2};" : "=l"(r) : "f"(lo), "f"(hi));
    return r;
}
__device__ __forceinline__ void unpackf2(unsigned long long v, float& lo, float& hi) {
    asm("mov.b64 {%0, %1}, %2;" : "=f"(lo), "=f"(hi) : "l"(v));
}
#define FMA2(acc, a, b) \
    asm("fma.rn.f32x2 %0, %1, %2, %0;" : "+l"(acc) : "l"(a), "l"(b))

__device__ __forceinline__ float gated_act(float f, float g) {
    float ef = __expf(2.f * f);
    float th = __fdividef(ef - 1.f, ef + 1.f);
    float sg = __fdividef(1.f, 1.f + __expf(-g));
    return th * sg;
}

// ---------------------------------------------------------------------------
__global__ __launch_bounds__(256) void k_adp(const float* __restrict__ nv1,
                                             const float* __restrict__ nv2,
                                             float* __restrict__ adpf,
                                             __half* __restrict__ Bpk) {
    __shared__ float red[256];
    int v = blockIdx.x, tid = threadIdx.x;
    float n1[10];
#pragma unroll
    for (int k = 0; k < 10; k++) n1[k] = nv1[v * 10 + k];
    float a[4];
#pragma unroll
    for (int j = 0; j < 4; j++) {
        int w = tid + j * 256;
        float s = 0.f;
#pragma unroll
        for (int k = 0; k < 10; k++) s += n1[k] * nv2[k * 1024 + w];
        a[j] = fmaxf(s, 0.f);
    }
    float mx = fmaxf(fmaxf(a[0], a[1]), fmaxf(a[2], a[3]));
    red[tid] = mx; __syncthreads();
    for (int s = 128; s > 0; s >>= 1) {
        if (tid < s) red[tid] = fmaxf(red[tid], red[tid + s]);
        __syncthreads();
    }
    mx = red[0]; __syncthreads();
    float e[4]; float sum = 0.f;
#pragma unroll
    for (int j = 0; j < 4; j++) { e[j] = expf(a[j] - mx); sum += e[j]; }
    red[tid] = sum; __syncthreads();
    for (int s = 128; s > 0; s >>= 1) {
        if (tid < s) red[tid] += red[tid + s];
        __syncthreads();
    }
    float inv = 1.f / red[0];
#pragma unroll
    for (int j = 0; j < 4; j++) {
        int w = tid + j * 256;
        float val = e[j] * inv;
        adpf[(long)v * 1024 + w] = val;
        Bpk[((long)(v >> 1) * 1024 + w) * 2 + (v & 1)] = __float2half(val);
    }
}

// ---------------------------------------------------------------------------
__global__ __launch_bounds__(256) void k_start(const float* __restrict__ x,
                                               const float* __restrict__ sw,
                                               const float* __restrict__ sb,
                                               float* __restrict__ h) {
    int bl = blockIdx.x;
    int b = bl / 13, l = bl - b * 13;
    int n = blockIdx.y * 256 + threadIdx.x;
    float x0 = x[(((long)b * 2 + 0) * 1024 + n) * 13 + l];
    float x1 = x[(((long)b * 2 + 1) * 1024 + n) * 13 + l];
    float* hb = h + ((long)(b * 13 + l) * 32) * 1024 + n;
#pragma unroll
    for (int c = 0; c < 32; c++)
        hb[(long)c * 1024] = sw[c * 2] * x0 + sw[c * 2 + 1] * x1 + sb[c];
}

// ---------------------------------------------------------------------------
// dilated conv + gated activation; m stored k-packed (premix now a GEMM).
// ---------------------------------------------------------------------------
__global__ __launch_bounds__(256) void k_dconv(const float* __restrict__ h,
                                               const float* __restrict__ fw,
                                               const float* __restrict__ fb,
                                               const float* __restrict__ gw,
                                               const float* __restrict__ gb,
                                               __half* __restrict__ mpk,
                                               __half* __restrict__ msk,
                                               int L0, int L1, int d, int layer,
                                               int doPk) {
    __shared__ float  s_in[2][32][64];
    __shared__ float4 s_wf[32][16];
    __shared__ float4 s_wg[32][16];
    __shared__ unsigned long long s_fbp[16], s_gbp[16];

    int bl = blockIdx.x;
    int b = bl / L1, l = bl - b * L1;
    int n0 = blockIdx.y * 64;
    int tid = threadIdx.x;

    for (int idx = tid; idx < 512; idx += 256) {
        int ci = idx >> 4, p = idx & 15;
        int co0 = p * 2, co1 = p * 2 + 1;
        int o0 = (co0 * 32 + ci) * 2, o1 = (co1 * 32 + ci) * 2;
        s_wf[ci][p] = make_float4(fw[o0], fw[o1], fw[o0 + 1], fw[o1 + 1]);
        s_wg[ci][p] = make_float4(gw[o0], gw[o1], gw[o0 + 1], gw[o1 + 1]);
    }
    if (tid < 16) {
        s_fbp[tid] = packf2(fb[2 * tid], fb[2 * tid + 1]);
        s_gbp[tid] = packf2(gb[2 * tid], gb[2 * tid + 1]);
    }
    const float* hb = h + ((long)(b * L0 + l) * 32) * 1024 + n0;
    for (int idx = tid; idx < 4096; idx += 256) {
        int tap = idx >> 11, ci = (idx >> 6) & 31, nl = idx & 63;
        s_in[tap][ci][nl] = hb[((long)(tap * d) * 32 + ci) * 1024 + nl];
    }
    __syncthreads();

    int nl = tid & 63, cg = tid >> 6;
    unsigned long long fa2[4], ga2[4];
#pragma unroll
    for (int p = 0; p < 4; p++) { fa2[p] = s_fbp[cg * 4 + p]; ga2[p] = s_gbp[cg * 4 + p]; }
#pragma unroll
    for (int ci = 0; ci < 32; ci++) {
        float v0 = s_in[0][ci][nl], v1 = s_in[1][ci][nl];
        unsigned long long vv0 = packf2(v0, v0), vv1 = packf2(v1, v1);
#pragma unroll
        for (int p = 0; p < 4; p++) {
            ulonglong2 wf = *(const ulonglong2*)&s_wf[ci][cg * 4 + p];
            FMA2(fa2[p], wf.x, vv0);
            FMA2(fa2[p], wf.y, vv1);
            ulonglong2 wg = *(const ulonglong2*)&s_wg[ci][cg * 4 + p];
            FMA2(ga2[p], wg.x, vv0);
            FMA2(ga2[p], wg.y, vv1);
        }
    }

    bool last = (l == L1 - 1);
    long col = (long)b * 1024 + n0 + nl;
    long colp = (long)(b * L1 + l) * 1024 + n0 + nl;   // packed-m column
    long ldp = (long)L1 * 65536;                        // packed-m row stride (half2)
    half2* mp = (half2*)mpk;
#pragma unroll
    for (int p = 0; p < 4; p++) {
        float flo, fhi, glo, ghi;
        unpackf2(fa2[p], flo, fhi);
        unpackf2(ga2[p], glo, ghi);
        float m0v = gated_act(flo, glo);
        float m1v = gated_act(fhi, ghi);
        if (doPk)
            mp[(long)(cg * 4 + p) * ldp + colp] = __floats2half2_rn(m0v, m1v);
        if (last) {
            int k0 = layer * 32 + cg * 8 + 2 * p;
            msk[((long)(k0 >> 1) * 65536 + col) * 2 + 0] = __float2half(m0v);
            msk[((long)(k0 >> 1) * 65536 + col) * 2 + 1] = __float2half(m1v);
        }
    }
}

// ---------------------------------------------------------------------------
// fp32 SIMT SGEMM: ADP^2 = ADP @ ADP; k-packed half into Bpk rows 512..1023
// ---------------------------------------------------------------------------
__global__ __launch_bounds__(256) void k_sgemm(const float* __restrict__ A,
                                               const float* __restrict__ B,
                                               __half* __restrict__ Bpk) {
    __shared__ float As[16][132];
    __shared__ float Bs[16][128];
    int tid = threadIdx.x;
    int m0 = blockIdx.y * 128, n0 = blockIdx.x * 128;
    int ty = tid >> 4, tx = tid & 15;
    float acc[8][8];
#pragma unroll
    for (int i = 0; i < 8; i++)
#pragma unroll
        for (int j = 0; j < 8; j++) acc[i][j] = 0.f;

    for (int k0 = 0; k0 < 1024; k0 += 16) {
#pragma unroll
        for (int i = 0; i < 2; i++) {
            int f = tid + i * 256;
            int r = f >> 2, kc = (f & 3) * 4;
            float4 v = *(const float4*)(A + (long)(m0 + r) * 1024 + k0 + kc);
            As[kc + 0][r] = v.x; As[kc + 1][r] = v.y;
            As[kc + 2][r] = v.z; As[kc + 3][r] = v.w;
        }
#pragma unroll
        for (int i = 0; i < 2; i++) {
            int f = tid + i * 256;
            int r = f >> 5, nc = (f & 31) * 4;
            float4 v = *(const float4*)(B + (long)(k0 + r) * 1024 + n0 + nc);
            *(float4*)&Bs[r][nc] = v;
        }
        __syncthreads();
#pragma unroll
        for (int k = 0; k < 16; k++) {
            float a[8], b[8];
            float4 a0 = *(const float4*)&As[k][ty * 8];
            float4 a1 = *(const float4*)&As[k][ty * 8 + 4];
            a[0] = a0.x; a[1] = a0.y; a[2] = a0.z; a[3] = a0.w;
            a[4] = a1.x; a[5] = a1.y; a[6] = a1.z; a[7] = a1.w;
            float4 b0 = *(const float4*)&Bs[k][tx * 8];
            float4 b1 = *(const float4*)&Bs[k][tx * 8 + 4];
            b[0] = b0.x; b[1] = b0.y; b[2] = b0.z; b[3] = b0.w;
            b[4] = b1.x; b[5] = b1.y; b[6] = b1.z; b[7] = b1.w;
#pragma unroll
            for (int i = 0; i < 8; i++)
#pragma unroll
                for (int j = 0; j < 8; j++) acc[i][j] += a[i] * b[j];
        }
        __syncthreads();
    }
#pragma unroll
    for (int i = 0; i < 8; i++) {
        int v = m0 + ty * 8 + i;
#pragma unroll
        for (int j = 0; j < 8; j++) {
            int w = n0 + tx * 8 + j;
            Bpk[((long)(512 + (v >> 1)) * 1024 + w) * 2 + (v & 1)] =
                __float2half(acc[i][j]);
        }
    }
}

// ---------------------------------------------------------------------------
// premix GEMM: [W1;W2;Wm;0] (128x32) @ mpk (32 x Ncols) -> mmA / mm0.
// Single K-chunk, grid (Ncols/256). Epilogue scatters by row block.
// ---------------------------------------------------------------------------
__global__ __launch_bounds__(256) void k_gemm_pre(const __half* __restrict__ A,
                                                  const half2* __restrict__ Bpk,
                                                  __half* __restrict__ mmA,
                                                  __half* __restrict__ mm0,
                                                  const float* __restrict__ gcb,
                                                  long ldb2) {
    __shared__ __half As[128][40];
    __shared__ half2  Bs[16][264];
    int tid = threadIdx.x;
    long n0 = (long)blockIdx.x * 256;
    int w = tid >> 5, lane = tid & 31;
    int grp = lane >> 2, tg = lane & 3;
    int wm = (w & 1) * 64, wn = (w >> 1) * 64;
    int arow = lane & 15, akoff = (lane >> 4) * 8;
    unsigned asBase = (unsigned)__cvta_generic_to_shared(&As[0][0]);

    // load A: 128 rows x 32 halves
    {
        int r = tid >> 1, p = (tid & 1) * 16;
        cp16(&As[r][p], A + r * 32 + p);
        cp16(&As[r][p + 8], A + r * 32 + p + 8);
    }
    // load B: 16 rows x 256 half2
#pragma unroll
    for (int i = 0; i < 4; i++) {
        int ch = tid + i * 256;
        int r = ch >> 6, c4 = (ch & 63) * 4;
        cp16(&Bs[r][c4], Bpk + (long)r * ldb2 + n0 + c4);
    }
    asm volatile("cp.async.commit_group;\n");
    asm volatile("cp.async.wait_group 0;\n");
    __syncthreads();

    float acc[4][8][4];
#pragma unroll
    for (int mt = 0; mt < 4; mt++)
#pragma unroll
        for (int nt = 0; nt < 8; nt++)
#pragma unroll
            for (int c = 0; c < 4; c++) acc[mt][nt][c] = 0.f;

#pragma unroll
    for (int s2 = 0; s2 < 2; s2++) {
        unsigned a[4][4];
#pragma unroll
        for (int mt = 0; mt < 4; mt++) {
            unsigned addr = asBase +
                (unsigned)((wm + mt * 16 + arow) * 40 + s2 * 16 + akoff) * 2;
            asm volatile(
                "ldmatrix.sync.aligned.m8n8.x4.shared.b16 {%0,%1,%2,%3}, [%4];\n"
                : "=r"(a[mt][0]), "=r"(a[mt][1]), "=r"(a[mt][2]), "=r"(a[mt][3])
                : "r"(addr));
        }
        unsigned b[8][2];
#pragma unroll
        for (int nt = 0; nt < 8; nt++) {
            int cb = wn + nt * 8 + grp;
            b[nt][0] = *(const unsigned*)&Bs[s2 * 8 + tg][cb];
            b[nt][1] = *(const unsigned*)&Bs[s2 * 8 + tg + 4][cb];
        }
#pragma unroll
        for (int mt = 0; mt < 4; mt++)
#pragma unroll
            for (int nt = 0; nt < 8; nt++) {
                asm volatile(
                    "mma.sync.aligned.m16n8k16.row.col.f32.f16.f16.f32 "
                    "{%0,%1,%2,%3}, {%4,%5,%6,%7}, {%8,%9}, {%0,%1,%2,%3};\n"
                    : "+f"(acc[mt][nt][0]), "+f"(acc[mt][nt][1]),
                      "+f"(acc[mt][nt][2]), "+f"(acc[mt][nt][3])
                    : "r"(a[mt][0]), "r"(a[mt][1]), "r"(a[mt][2]), "r"(a[mt][3]),
                      "r"(b[nt][0]), "r"(b[nt][1]));
            }
    }

    // epilogue: rows 0-31 -> mm1 (mmA col 0), 32-63 -> mm2 (mmA +1024),
    // 64-95 -> mm0 + gcb, 96-127 -> skip.
#pragma unroll
    for (int mt = 0; mt < 4; mt++) {
        int row0 = wm + mt * 16 + grp;
        int row1 = row0 + 8;
#pragma unroll
        for (int nt = 0; nt < 8; nt++) {
            long col = n0 + wn + nt * 8 + tg * 2;
            long bl = col >> 10;
            long n = col & 1023;
#pragma unroll
            for (int rr = 0; rr < 2; rr++) {
                int row = rr ? row1 : row0;
                float v0 = acc[mt][nt][rr * 2 + 0];
                float v1 = acc[mt][nt][rr * 2 + 1];
                int blkr = row >> 5, co = row & 31;
                if (blkr == 0) {
                    *(half2*)&mmA[(bl * 32 + co) * 2048 + n] =
                        __floats2half2_rn(v0, v1);
                } else if (blkr == 1) {
                    *(half2*)&mmA[(bl * 32 + co) * 2048 + 1024 + n] =
                        __floats2half2_rn(v0, v1);
                } else if (blkr == 2) {
                    float bv = gcb[co];
                    *(half2*)&mm0[(bl * 32 + co) * 1024 + n] =
                        __floats2half2_rn(v0 + bv, v1 + bv);
                }
            }
        }
    }
}

// ---------------------------------------------------------------------------
// gc-tail epilogue helper
// ---------------------------------------------------------------------------
__device__ __forceinline__ void gc_epilogue_rowpair(
    float* hnew, const float* hold, const __half* mm0,
    const float* bng, const float* bnb,
    int L0, int L1, int d, int row0, int wn_base, int n0, int tg,
    const float (*accRow)[4], int ntcount) {
    const float rs = rsqrtf(1.f + 1e-5f);
    int row1 = row0 + 8;
    int blx = row0 >> 5;
    int b = blx / L1, l = blx - b * L1;
    long hbase = (long)(b * L0 + l + d) * 32;
    int co0 = row0 & 31, co1 = row1 & 31;
    float sc0 = bng[co0] * rs, sh0 = bnb[co0];
    float sc1 = bng[co1] * rs, sh1 = bnb[co1];
    for (int nt = 0; nt < ntcount; nt++) {
        int col = n0 + wn_base + nt * 8 + tg * 2;
        half2 q0 = *(const half2*)&mm0[(long)row0 * 1024 + col];
        half2 q1 = *(const half2*)&mm0[(long)row1 * 1024 + col];
        float2 r0 = *(const float2*)&hold[(hbase + co0) * 1024 + col];
        float2 r1 = *(const float2*)&hold[(hbase + co1) * 1024 + col];
        float2 o0, o1;
        o0.x = (accRow[nt][0] + __half2float(q0.x) + r0.x) * sc0 + sh0;
        o0.y = (accRow[nt][1] + __half2float(q0.y) + r0.y) * sc0 + sh0;
        o1.x = (accRow[nt][2] + __half2float(q1.x) + r1.x) * sc1 + sh1;
        o1.y = (accRow[nt][3] + __half2float(q1.y) + r1.y) * sc1 + sh1;
        *(float2*)&hnew[(long)row0 * 1024 + col] = o0;
        *(float2*)&hnew[(long)row1 * 1024 + col] = o1;
    }
}

// ---------------------------------------------------------------------------
// fused layer GEMM + gc tail, BN=256 (large-M layers).
// ---------------------------------------------------------------------------
__global__ __launch_bounds__(256) void k_gemm_gc(const __half* __restrict__ A,
                                                 const half2* __restrict__ Bpk,
                                                 float* __restrict__ hnew,
                                                 const float* __restrict__ hold,
                                                 const __half* __restrict__ mm0,
                                                 const float* __restrict__ bng,
                                                 const float* __restrict__ bnb,
                                                 int L0, int L1, int d) {
    __shared__ __half As[2][128][40];
    __shared__ half2  Bs[2][16][264];
    int tid = threadIdx.x;
    int m0 = blockIdx.y * 128;
    int n0 = blockIdx.x * 256;
    int w = tid >> 5, lane = tid & 31;
    int grp = lane >> 2, tg = lane & 3;
    int wm = (w & 1) * 64, wn = (w >> 1) * 64;
    int arow = lane & 15, akoff = (lane >> 4) * 8;
    unsigned asBase = (unsigned)__cvta_generic_to_shared(&As[0][0][0]);

    float acc[4][8][4];
#pragma unroll
    for (int mt = 0; mt < 4; mt++)
#pragma unroll
        for (int nt = 0; nt < 8; nt++)
#pragma unroll
            for (int c = 0; c < 4; c++) acc[mt][nt][c] = 0.f;

    const int nstage = 2048 / 32;
    {
#pragma unroll
        for (int i = 0; i < 2; i++) {
            int ch = tid + i * 256;
            int r = ch >> 2, p = (ch & 3) * 8;
            cp16(&As[0][r][p], A + (long)(m0 + r) * 2048 + p);
        }
#pragma unroll
        for (int i = 0; i < 4; i++) {
            int ch = tid + i * 256;
            int r = ch >> 6, c4 = (ch & 63) * 4;
            cp16(&Bs[0][r][c4], Bpk + (long)r * 1024 + n0 + c4);
        }
        asm volatile("cp.async.commit_group;\n");
    }

    for (int s = 0; s < nstage; s++) {
        int buf = s & 1;
        if (s + 1 < nstage) {
            int nb = buf ^ 1;
            int k0 = (s + 1) * 32;
#pragma unroll
            for (int i = 0; i < 2; i++) {
                int ch = tid + i * 256;
                int r = ch >> 2, p = (ch & 3) * 8;
                cp16(&As[nb][r][p], A + (long)(m0 + r) * 2048 + k0 + p);
            }
#pragma unroll
            for (int i = 0; i < 4; i++) {
                int ch = tid + i * 256;
                int r = ch >> 6, c4 = (ch & 63) * 4;
                cp16(&Bs[nb][r][c4], Bpk + (long)(k0 / 2 + r) * 1024 + n0 + c4);
            }
            asm volatile("cp.async.commit_group;\n");
            asm volatile("cp.async.wait_group 1;\n");
        } else {
            asm volatile("cp.async.wait_group 0;\n");
        }
        __syncthreads();

#pragma unroll
        for (int s2 = 0; s2 < 2; s2++) {
            unsigned a[4][4];
#pragma unroll
            for (int mt = 0; mt < 4; mt++) {
                unsigned addr = asBase +
                    (unsigned)(((buf << 7) + wm + mt * 16 + arow) * 40 +
                               s2 * 16 + akoff) * 2;
                asm volatile(
                    "ldmatrix.sync.aligned.m8n8.x4.shared.b16 {%0,%1,%2,%3}, [%4];\n"
                    : "=r"(a[mt][0]), "=r"(a[mt][1]), "=r"(a[mt][2]), "=r"(a[mt][3])
                    : "r"(addr));
            }
            unsigned b[8][2];
#pragma unroll
            for (int nt = 0; nt < 8; nt++) {
                int cb = wn + nt * 8 + grp;
                b[nt][0] = *(const unsigned*)&Bs[buf][s2 * 8 + tg][cb];
                b[nt][1] = *(const unsigned*)&Bs[buf][s2 * 8 + tg + 4][cb];
            }
#pragma unroll
            for (int mt = 0; mt < 4; mt++)
#pragma unroll
                for (int nt = 0; nt < 8; nt++) {
                    asm volatile(
                        "mma.sync.aligned.m16n8k16.row.col.f32.f16.f16.f32 "
                        "{%0,%1,%2,%3}, {%4,%5,%6,%7}, {%8,%9}, {%0,%1,%2,%3};\n"
                        : "+f"(acc[mt][nt][0]), "+f"(acc[mt][nt][1]),
                          "+f"(acc[mt][nt][2]), "+f"(acc[mt][nt][3])
                        : "r"(a[mt][0]), "r"(a[mt][1]), "r"(a[mt][2]), "r"(a[mt][3]),
                          "r"(b[nt][0]), "r"(b[nt][1]));
                }
        }
        __syncthreads();
    }

#pragma unroll
    for (int mt = 0; mt < 4; mt++)
        gc_epilogue_rowpair(hnew, hold, mm0, bng, bnb, L0, L1, d,
                            m0 + wm + mt * 16 + grp, wn, n0, tg, acc[mt], 8);
}

// ---------------------------------------------------------------------------
// fused layer GEMM + gc tail, BN=128 (small-M layers).
// ---------------------------------------------------------------------------
__global__ __launch_bounds__(256) void k_gemm_gc128(const __half* __restrict__ A,
                                                    const half2* __restrict__ Bpk,
                                                    float* __restrict__ hnew,
                                                    const float* __restrict__ hold,
                                                    const __half* __restrict__ mm0,
                                                    const float* __restrict__ bng,
                                                    const float* __restrict__ bnb,
                                                    int L0, int L1, int d) {
    __shared__ __half As[2][128][40];
    __shared__ half2  Bs[2][16][136];
    int tid = threadIdx.x;
    int m0 = blockIdx.y * 128;
    int n0 = blockIdx.x * 128;
    int w = tid >> 5, lane = tid & 31;
    int grp = lane >> 2, tg = lane & 3;
    int wm = (w & 3) * 32, wn = (w >> 2) * 64;
    int arow = lane & 15, akoff = (lane >> 4) * 8;
    unsigned asBase = (unsigned)__cvta_generic_to_shared(&As[0][0][0]);

    float acc[2][8][4];
#pragma unroll
    for (int mt = 0; mt < 2; mt++)
#pragma unroll
        for (int nt = 0; nt < 8; nt++)
#pragma unroll
            for (int c = 0; c < 4; c++) acc[mt][nt][c] = 0.f;

    const int nstage = 2048 / 32;
    {
#pragma unroll
        for (int i = 0; i < 2; i++) {
            int ch = tid + i * 256;
            int r = ch >> 2, p = (ch & 3) * 8;
            cp16(&As[0][r][p], A + (long)(m0 + r) * 2048 + p);
        }
#pragma unroll
        for (int i = 0; i < 2; i++) {
            int ch = tid + i * 256;
            int r = ch >> 5, c4 = (ch & 31) * 4;
            cp16(&Bs[0][r][c4], Bpk + (long)r * 1024 + n0 + c4);
        }
        asm volatile("cp.async.commit_group;\n");
    }

    for (int s = 0; s < nstage; s++) {
        int buf = s & 1;
        if (s + 1 < nstage) {
            int nb = buf ^ 1;
            int k0 = (s + 1) * 32;
#pragma unroll
            for (int i = 0; i < 2; i++) {
                int ch = tid + i * 256;
                int r = ch >> 2, p = (ch & 3) * 8;
                cp16(&As[nb][r][p], A + (long)(m0 + r) * 2048 + k0 + p);
            }
#pragma unroll
            for (int i = 0; i < 2; i++) {
                int ch = tid + i * 256;
                int r = ch >> 5, c4 = (ch & 31) * 4;
                cp16(&Bs[nb][r][c4], Bpk + (long)(k0 / 2 + r) * 1024 + n0 + c4);
            }
            asm volatile("cp.async.commit_group;\n");
            asm volatile("cp.async.wait_group 1;\n");
        } else {
            asm volatile("cp.async.wait_group 0;\n");
        }
        __syncthreads();

#pragma unroll
        for (int s2 = 0; s2 < 2; s2++) {
            unsigned a[2][4];
#pragma unroll
            for (int mt = 0; mt < 2; mt++) {
                unsigned addr = asBase +
                    (unsigned)(((buf << 7) + wm + mt * 16 + arow) * 40 +
                               s2 * 16 + akoff) * 2;
                asm volatile(
                    "ldmatrix.sync.aligned.m8n8.x4.shared.b16 {%0,%1,%2,%3}, [%4];\n"
                    : "=r"(a[mt][0]), "=r"(a[mt][1]), "=r"(a[mt][2]), "=r"(a[mt][3])
                    : "r"(addr));
            }
            unsigned b[8][2];
#pragma unroll
            for (int nt = 0; nt < 8; nt++) {
                int cb = wn + nt * 8 + grp;
                b[nt][0] = *(const unsigned*)&Bs[buf][s2 * 8 + tg][cb];
                b[nt][1] = *(const unsigned*)&Bs[buf][s2 * 8 + tg + 4][cb];
            }
#pragma unroll
            for (int mt = 0; mt < 2; mt++)
#pragma unroll
                for (int nt = 0; nt < 8; nt++) {
                    asm volatile(
                        "mma.sync.aligned.m16n8k16.row.col.f32.f16.f16.f32 "
                        "{%0,%1,%2,%3}, {%4,%5,%6,%7}, {%8,%9}, {%0,%1,%2,%3};\n"
                        : "+f"(acc[mt][nt][0]), "+f"(acc[mt][nt][1]),
                          "+f"(acc[mt][nt][2]), "+f"(acc[mt][nt][3])
                        : "r"(a[mt][0]), "r"(a[mt][1]), "r"(a[mt][2]), "r"(a[mt][3]),
                          "r"(b[nt][0]), "r"(b[nt][1]));
                }
        }
        __syncthreads();
    }

#pragma unroll
    for (int mt = 0; mt < 2; mt++)
        gc_epilogue_rowpair(hnew, hold, mm0, bng, bnb, L0, L1, d,
                            m0 + wm + mt * 16 + grp, wn, n0, tg, acc[mt], 8);
}

// ---------------------------------------------------------------------------
// generic fp16 GEMM (skip/end1/end2). flags as before.
// ---------------------------------------------------------------------------
__global__ __launch_bounds__(256) void k_gemm_f16(const __half* __restrict__ A,
                                                  const half2* __restrict__ Bpk,
                                                  void* __restrict__ Cv,
                                                  int K, int lda, long ldb2, long ldc,
                                                  const float* __restrict__ bias,
                                                  int flags) {
    __shared__ __half As[2][128][40];
    __shared__ half2  Bs[2][16][264];
    int tid = threadIdx.x;
    int m0 = blockIdx.y * 128;
    long n0 = (long)blockIdx.x * 256;
    int w = tid >> 5, lane = tid & 31;
    int grp = lane >> 2, tg = lane & 3;
    int wm = (w & 1) * 64, wn = (w >> 1) * 64;
    int arow = lane & 15, akoff = (lane >> 4) * 8;
    unsigned asBase = (unsigned)__cvta_generic_to_shared(&As[0][0][0]);

    float acc[4][8][4];
#pragma unroll
    for (int mt = 0; mt < 4; mt++)
#pragma unroll
        for (int nt = 0; nt < 8; nt++)
#pragma unroll
            for (int c = 0; c < 4; c++) acc[mt][nt][c] = 0.f;

    int nstage = K / 32;
    {
#pragma unroll
        for (int i = 0; i < 2; i++) {
            int ch = tid + i * 256;
            int r = ch >> 2, p = (ch & 3) * 8;
            cp16(&As[0][r][p], A + (long)(m0 + r) * lda + p);
        }
#pragma unroll
        for (int i = 0; i < 4; i++) {
            int ch = tid + i * 256;
            int r = ch >> 6, c4 = (ch & 63) * 4;
            cp16(&Bs[0][r][c4], Bpk + (long)r * ldb2 + n0 + c4);
        }
        asm volatile("cp.async.commit_group;\n");
    }

    for (int s = 0; s < nstage; s++) {
        int buf = s & 1;
        if (s + 1 < nstage) {
            int nb = buf ^ 1;
            int k0 = (s + 1) * 32;
#pragma unroll
            for (int i = 0; i < 2; i++) {
                int ch = tid + i * 256;
                int r = ch >> 2, p = (ch & 3) * 8;
                cp16(&As[nb][r][p], A + (long)(m0 + r) * lda + k0 + p);
            }
#pragma unroll
            for (int i = 0; i < 4; i++) {
                int ch = tid + i * 256;
                int r = ch >> 6, c4 = (ch & 63) * 4;
                cp16(&Bs[nb][r][c4], Bpk + (long)(k0 / 2 + r) * ldb2 + n0 + c4);
            }
            asm volatile("cp.async.commit_group;\n");
            asm volatile("cp.async.wait_group 1;\n");
        } else {
            asm volatile("cp.async.wait_group 0;\n");
        }
        __syncthreads();

#pragma unroll
        for (int s2 = 0; s2 < 2; s2++) {
            unsigned a[4][4];
#pragma unroll
            for (int mt = 0; mt < 4; mt++) {
                unsigned addr = asBase +
                    (unsigned)(((buf << 7) + wm + mt * 16 + arow) * 40 +
                               s2 * 16 + akoff) * 2;
                asm volatile(
                    "ldmatrix.sync.aligned.m8n8.x4.shared.b16 {%0,%1,%2,%3}, [%4];\n"
                    : "=r"(a[mt][0]), "=r"(a[mt][1]), "=r"(a[mt][2]), "=r"(a[mt][3])
                    : "r"(addr));
            }
            unsigned b[8][2];
#pragma unroll
            for (int nt = 0; nt < 8; nt++) {
                int cb = wn + nt * 8 + grp;
                b[nt][0] = *(const unsigned*)&Bs[buf][s2 * 8 + tg][cb];
                b[nt][1] = *(const unsigned*)&Bs[buf][s2 * 8 + tg + 4][cb];
            }
#pragma unroll
            for (int mt = 0; mt < 4; mt++)
#pragma unroll
                for (int nt = 0; nt < 8; nt++) {
                    asm volatile(
                        "mma.sync.aligned.m16n8k16.row.col.f32.f16.f16.f32 "
                        "{%0,%1,%2,%3}, {%4,%5,%6,%7}, {%8,%9}, {%0,%1,%2,%3};\n"
                        : "+f"(acc[mt][nt][0]), "+f"(acc[mt][nt][1]),
                          "+f"(acc[mt][nt][2]), "+f"(acc[mt][nt][3])
                        : "r"(a[mt][0]), "r"(a[mt][1]), "r"(a[mt][2]), "r"(a[mt][3]),
                          "r"(b[nt][0]), "r"(b[nt][1]));
                }
        }
        __syncthreads();
    }

    float* Cf = (float*)Cv;
    __half* Ch = (__half*)Cv;
#pragma unroll
    for (int mt = 0; mt < 4; mt++) {
        int row0 = m0 + wm + mt * 16 + grp;
        int row1 = row0 + 8;
        float b0 = 0.f, b1 = 0.f;
        if (flags & (2 | 16)) { b0 = bias[row0]; b1 = bias[row1]; }
#pragma unroll
        for (int nt = 0; nt < 8; nt++) {
            long col = n0 + wn + nt * 8 + tg * 2;
            float v00 = acc[mt][nt][0], v01 = acc[mt][nt][1];
            float v10 = acc[mt][nt][2], v11 = acc[mt][nt][3];
            if (flags & 2) {
                v00 = fmaxf(v00 + b0, 0.f); v01 = fmaxf(v01 + b0, 0.f);
                v10 = fmaxf(v10 + b1, 0.f); v11 = fmaxf(v11 + b1, 0.f);
            } else if (flags & 16) {
                v00 += b0; v01 += b0; v10 += b1; v11 += b1;
            }
            if (flags & 16) {
                long bidx = col >> 10;
                long n = col & 1023;
                if (row0 < 12)
                    *(float2*)(Cf + (bidx * 12 + row0) * 1024 + n) =
                        make_float2(v00, v01);
                if (row1 < 12)
                    *(float2*)(Cf + (bidx * 12 + row1) * 1024 + n) =
                        make_float2(v10, v11);
            } else if (flags & 4) {
                long p0 = ((long)(row0 >> 1) * ldc + col) * 2 + (row0 & 1);
                long p1 = ((long)(row1 >> 1) * ldc + col) * 2 + (row1 & 1);
                Ch[p0] = __float2half(v00); Ch[p0 + 2] = __float2half(v01);
                Ch[p1] = __float2half(v10); Ch[p1 + 2] = __float2half(v11);
            } else if (flags & 8) {
                *(half2*)(Ch + (long)row0 * ldc + col) = __floats2half2_rn(v00, v01);
                *(half2*)(Ch + (long)row1 * ldc + col) = __floats2half2_rn(v10, v11);
            } else {
                *(float2*)(Cf + (long)row0 * ldc + col) = make_float2(v00, v01);
                *(float2*)(Cf + (long)row1 * ldc + col) = make_float2(v10, v11);
            }
        }
    }
}

// ---------------------------------------------------------------------------
// merged prep. blocks: [0,512) end1_w round; [512,768) skip wcat+bias;
// [768,896) end2 pad; [896,1792) premix weights (7 layers x 128 rows).
// ---------------------------------------------------------------------------
__global__ __launch_bounds__(256) void k_prep_all(const float* __restrict__ end1_w,
                                                  const float* __restrict__ skw,
                                                  const float* __restrict__ skb,
                                                  const float* __restrict__ w2,
                                                  const float* __restrict__ b2,
                                                  const float* __restrict__ gcw,
                                                  __half* __restrict__ w1r,
                                                  __half* __restrict__ wcat,
                                                  float* __restrict__ bsum,
                                                  __half* __restrict__ w2p,
                                                  float* __restrict__ b2p,
                                                  __half* __restrict__ wgc) {
    int blk = blockIdx.x;
    int tid = threadIdx.x;
    if (blk < 512) {
        int i = blk * 256 + tid;
        w1r[i] = __float2half(end1_w[i]);
    } else if (blk < 768) {
        int co = blk - 512, k = tid;
        int i = k >> 5, ci = k & 31;
        wcat[co * 256 + k] = __float2half(skw[((long)i * 256 + co) * 32 + ci]);
        if (k == 0) {
            float s = 0.f;
#pragma unroll
            for (int j = 0; j < 8; j++) s += skb[j * 256 + co];
            bsum[co] = s;
        }
    } else if (blk < 896) {
        int o = blk - 768;
#pragma unroll
        for (int i = 0; i < 2; i++) {
            int k = tid + i * 256;
            w2p[o * 512 + k] = (o < 12) ? __float2half(w2[o * 512 + k])
                                        : __float2half(0.f);
        }
        if (tid == 0) b2p[o] = (o < 12) ? b2[o] : 0.f;
    } else {
        int rid = blk - 896;                 // 0..895
        int layer = rid >> 7, row = rid & 127;
        if (tid < 32) {
            int ci = tid, co = row & 31;
            float v = 0.f;
            const float* g = gcw + (long)layer * 32 * 96 + co * 96;
            if (row < 32)       v = g[32 + ci];   // W_x1 -> mm1
            else if (row < 64)  v = g[64 + ci];   // W_x2 -> mm2
            else if (row < 96)  v = g[ci];        // W_m  -> mm0
            wgc[(long)layer * 4096 + row * 32 + ci] = __float2half(v);
        }
    }
}

// ---------------------------------------------------------------------------
extern "C" void kernel_launch(void* const* d_in, const int* in_sizes, int n_in,
                              void* d_out, int out_size) {
    const float* x        = (const float*)d_in[0];
    const float* start_w  = (const float*)d_in[1];
    const float* start_b  = (const float*)d_in[2];
    const float* nodevec1 = (const float*)d_in[3];
    const float* nodevec2 = (const float*)d_in[4];
    const float* filter_w = (const float*)d_in[5];
    const float* filter_b = (const float*)d_in[6];
    const float* gate_w   = (const float*)d_in[7];
    const float* gate_b   = (const float*)d_in[8];
    const float* skip_w   = (const float*)d_in[9];
    const float* skip_b   = (const float*)d_in[10];
    const float* gc_w     = (const float*)d_in[11];
    const float* gc_b     = (const float*)d_in[12];
    const float* bn_g     = (const float*)d_in[13];
    const float* bn_b     = (const float*)d_in[14];
    const float* end1_w   = (const float*)d_in[15];
    const float* end1_b   = (const float*)d_in[16];
    const float* end2_w   = (const float*)d_in[17];
    const float* end2_b   = (const float*)d_in[18];

    float *hA, *hB, *adpf, *bsk, *b2p;
    __half *mmA, *mm0, *mpk, *Bm, *msk, *skip, *e1, *w1r, *wsk, *w2p, *wgc;
    cudaGetSymbolAddress((void**)&hA, g_hA);
    cudaGetSymbolAddress((void**)&hB, g_hB);
    cudaGetSymbolAddress((void**)&mmA, g_mmA);
    cudaGetSymbolAddress((void**)&mm0, g_mm0);
    cudaGetSymbolAddress((void**)&mpk, g_mpk);
    cudaGetSymbolAddress((void**)&adpf, g_adpf);
    cudaGetSymbolAddress((void**)&Bm, g_Bm);
    cudaGetSymbolAddress((void**)&msk, g_msk);
    cudaGetSymbolAddress((void**)&skip, g_skip);
    cudaGetSymbolAddress((void**)&e1, g_e1);
    cudaGetSymbolAddress((void**)&w1r, g_w1r);
    cudaGetSymbolAddress((void**)&wsk, g_wsk);
    cudaGetSymbolAddress((void**)&bsk, g_bsk);
    cudaGetSymbolAddress((void**)&w2p, g_w2p);
    cudaGetSymbolAddress((void**)&b2p, g_b2p);
    cudaGetSymbolAddress((void**)&wgc, g_wgc);

    k_adp<<<1024, 256>>>(nodevec1, nodevec2, adpf, Bm);
    k_sgemm<<<dim3(8, 8), 256>>>(adpf, adpf, Bm);
    k_start<<<dim3(64 * 13, 4), 256>>>(x, start_w, start_b, hA);
    k_prep_all<<<1792, 256>>>(end1_w, skip_w, skip_b, end2_w, end2_b, gc_w,
                              w1r, wsk, bsk, w2p, b2p, wgc);

    const int lens[9] = {13, 12, 10, 9, 7, 6, 4, 3, 1};
    const int dil[8]  = {1, 2, 1, 2, 1, 2, 1, 2};
    float* hcur = hA;
    float* hnext = hB;

    for (int i = 0; i < 8; i++) {
        int L0 = lens[i], L1 = lens[i + 1], d = dil[i];
        int doPk = (i < 7) ? 1 : 0;
        k_dconv<<<dim3(64 * L1, 16), 256>>>(hcur,
                                            filter_w + i * 2048, filter_b + i * 32,
                                            gate_w + i * 2048, gate_b + i * 32,
                                            mpk, msk, L0, L1, d, i, doPk);
        if (i < 7) {
            long Ncols = (long)L1 * 65536;
            // premix on tensor cores: mmA/mm0 from m
            k_gemm_pre<<<(int)(Ncols / 256), 256>>>(
                wgc + (long)i * 4096, (const half2*)mpk, mmA, mm0,
                gc_b + i * 32, Ncols);
            int M = 2048 * L1;
            if (L1 <= 7) {
                k_gemm_gc128<<<dim3(8, M / 128), 256>>>(
                    mmA, (const half2*)Bm, hnext, hcur, mm0,
                    bn_g + i * 32, bn_b + i * 32, L0, L1, d);
            } else {
                k_gemm_gc<<<dim3(4, M / 128), 256>>>(
                    mmA, (const half2*)Bm, hnext, hcur, mm0,
                    bn_g + i * 32, bn_b + i * 32, L0, L1, d);
            }
            float* t = hcur; hcur = hnext; hnext = t;
        }
    }

    // skip = relu(Wcat @ msk + bsum), k-packed half
    k_gemm_f16<<<dim3(65536 / 256, 2), 256>>>(
        wsk, (const half2*)msk, skip, 256, 256, 65536, 65536, bsk, 2 | 4);
    // e1 = relu(W1 @ skip + b1), k-packed half
    k_gemm_f16<<<dim3(65536 / 256, 4), 256>>>(
        w1r, (const half2*)skip, e1, 256, 256, 65536, 65536, end1_b, 2 | 4);
    // out = W2 @ e1 + b2
    k_gemm_f16<<<dim3(65536 / 256, 1), 256>>>(
        w2p, (const half2*)e1, (float*)d_out, 512, 512, 65536, 0, b2p, 16);
}